// round 1
// baseline (speedup 1.0000x reference)
#include <cuda_runtime.h>

// ---------------------------------------------------------------------------
// Problem constants (fixed shapes)
// ---------------------------------------------------------------------------
#define S      4096
#define DIMM   4096
#define HQ     32
#define HKV    8
#define HD     128
#define NQKV   6144          // (HQ + 2*HKV) * HD
#define TB     512           // S / 8 blocks
#define SINKB  4             // ceil(30/8)
#define WINST  508           // window start block
#define MBTOP  100           // heavy blocks
#define KLBLK  108           // 4 sink + 4 window + 100 heavy
#define KSEL   (KLBLK * 8)   // 864 selected tokens per head
#define NEGF   (-1e30f)
#define SCALE  0.08838834764831845f   // 1/sqrt(128)

// ---------------------------------------------------------------------------
// Scratch (static device globals — no runtime allocation allowed)
// ---------------------------------------------------------------------------
__device__ float g_qkv[(size_t)S * NQKV];     // qkv projections (q/k roped in-place)
__device__ float g_attn[(size_t)S * DIMM];    // attention output (S, H*D)
__device__ float g_krep[TB * HKV * HD];       // per-block mean keys
__device__ float g_qmean[HQ * HD];            // mean query per head
__device__ int   g_blk[HQ * KLBLK];           // selected block ids per head

// ---------------------------------------------------------------------------
// SGEMM  C[M,N] = A[M,K] @ B[N,K]^T   (both row-major, K contiguous)
// 128x128 tile, BK=16, 256 threads, 8x8 per thread, double-buffered smem.
// Requires M%128==0, N%128==0, K%16==0.
// ---------------------------------------------------------------------------
__global__ __launch_bounds__(256)
void sgemm_nt(const float* __restrict__ A, const float* __restrict__ B,
              float* __restrict__ C, int M, int N, int K)
{
    __shared__ float As[2][16][128];
    __shared__ float Bs[2][16][128];

    const int tid = threadIdx.x;
    const int tx  = tid & 15;
    const int ty  = tid >> 4;
    const int bm  = blockIdx.y << 7;
    const int bn  = blockIdx.x << 7;

    const int lr = tid >> 2;           // 0..63
    const int lk = (tid & 3) << 2;     // 0,4,8,12

    const float* Ap0 = A + (size_t)(bm + lr)      * K + lk;
    const float* Ap1 = A + (size_t)(bm + lr + 64) * K + lk;
    const float* Bp0 = B + (size_t)(bn + lr)      * K + lk;
    const float* Bp1 = B + (size_t)(bn + lr + 64) * K + lk;

    float acc[8][8];
#pragma unroll
    for (int i = 0; i < 8; i++)
#pragma unroll
        for (int j = 0; j < 8; j++) acc[i][j] = 0.f;

    float4 ra0 = *(const float4*)(Ap0);
    float4 ra1 = *(const float4*)(Ap1);
    float4 rb0 = *(const float4*)(Bp0);
    float4 rb1 = *(const float4*)(Bp1);

    int buf = 0;
    As[0][lk+0][lr]    = ra0.x; As[0][lk+1][lr]    = ra0.y;
    As[0][lk+2][lr]    = ra0.z; As[0][lk+3][lr]    = ra0.w;
    As[0][lk+0][lr+64] = ra1.x; As[0][lk+1][lr+64] = ra1.y;
    As[0][lk+2][lr+64] = ra1.z; As[0][lk+3][lr+64] = ra1.w;
    Bs[0][lk+0][lr]    = rb0.x; Bs[0][lk+1][lr]    = rb0.y;
    Bs[0][lk+2][lr]    = rb0.z; Bs[0][lk+3][lr]    = rb0.w;
    Bs[0][lk+0][lr+64] = rb1.x; Bs[0][lk+1][lr+64] = rb1.y;
    Bs[0][lk+2][lr+64] = rb1.z; Bs[0][lk+3][lr+64] = rb1.w;
    __syncthreads();

    const int nt = K >> 4;
    for (int t = 0; t < nt; ++t) {
        if (t + 1 < nt) {
            const int ko = (t + 1) << 4;
            ra0 = *(const float4*)(Ap0 + ko);
            ra1 = *(const float4*)(Ap1 + ko);
            rb0 = *(const float4*)(Bp0 + ko);
            rb1 = *(const float4*)(Bp1 + ko);
        }
#pragma unroll
        for (int k = 0; k < 16; ++k) {
            float4 a0 = *(const float4*)&As[buf][k][ty << 3];
            float4 a1 = *(const float4*)&As[buf][k][(ty << 3) + 4];
            float4 b0 = *(const float4*)&Bs[buf][k][tx << 3];
            float4 b1 = *(const float4*)&Bs[buf][k][(tx << 3) + 4];
            float av[8] = {a0.x, a0.y, a0.z, a0.w, a1.x, a1.y, a1.z, a1.w};
            float bv[8] = {b0.x, b0.y, b0.z, b0.w, b1.x, b1.y, b1.z, b1.w};
#pragma unroll
            for (int i = 0; i < 8; ++i)
#pragma unroll
                for (int j = 0; j < 8; ++j)
                    acc[i][j] += av[i] * bv[j];
        }
        if (t + 1 < nt) {
            buf ^= 1;
            As[buf][lk+0][lr]    = ra0.x; As[buf][lk+1][lr]    = ra0.y;
            As[buf][lk+2][lr]    = ra0.z; As[buf][lk+3][lr]    = ra0.w;
            As[buf][lk+0][lr+64] = ra1.x; As[buf][lk+1][lr+64] = ra1.y;
            As[buf][lk+2][lr+64] = ra1.z; As[buf][lk+3][lr+64] = ra1.w;
            Bs[buf][lk+0][lr]    = rb0.x; Bs[buf][lk+1][lr]    = rb0.y;
            Bs[buf][lk+2][lr]    = rb0.z; Bs[buf][lk+3][lr]    = rb0.w;
            Bs[buf][lk+0][lr+64] = rb1.x; Bs[buf][lk+1][lr+64] = rb1.y;
            Bs[buf][lk+2][lr+64] = rb1.z; Bs[buf][lk+3][lr+64] = rb1.w;
            __syncthreads();
        }
    }

#pragma unroll
    for (int i = 0; i < 8; ++i) {
        float* cp = C + (size_t)(bm + (ty << 3) + i) * N + bn + (tx << 3);
        float4 c0 = make_float4(acc[i][0], acc[i][1], acc[i][2], acc[i][3]);
        float4 c1 = make_float4(acc[i][4], acc[i][5], acc[i][6], acc[i][7]);
        *(float4*)cp       = c0;
        *(float4*)(cp + 4) = c1;
    }
}

// ---------------------------------------------------------------------------
// RoPE in-place on q and k slices of g_qkv. one thread per (s, head40, pair)
// ---------------------------------------------------------------------------
__global__ void rope_kernel(const float* __restrict__ fc)
{
    const int total = S * 40 * 64;
    int tid = blockIdx.x * blockDim.x + threadIdx.x;
    if (tid >= total) return;
    int j  = tid & 63;
    int r  = tid >> 6;
    int hh = r % 40;          // 0..31 = q heads, 32..39 = k heads
    int s  = r / 40;
    float* p = &g_qkv[(size_t)s * NQKV + hh * HD + (j << 1)];
    float f0 = fc[s * HD + (j << 1)];
    float f1 = fc[s * HD + (j << 1) + 1];
    float x0 = p[0], x1 = p[1];
    p[0] = x0 * f0 - x1 * f1;
    p[1] = x1 * f0 + x0 * f1;
}

// ---------------------------------------------------------------------------
// Per-block key means (8 tokens per block)
// ---------------------------------------------------------------------------
__global__ void kmean_kernel()
{
    int idx = blockIdx.x * blockDim.x + threadIdx.x;   // TB*HKV*HD threads
    int d  = idx & 127;
    int hl = (idx >> 7) & 7;
    int t  = idx >> 10;
    const float* p = &g_qkv[(size_t)(t * 8) * NQKV + HQ * HD + hl * HD + d];
    float s = 0.f;
#pragma unroll
    for (int i = 0; i < 8; ++i) s += p[(size_t)i * NQKV];
    g_krep[idx] = s * 0.125f;
}

// ---------------------------------------------------------------------------
// Mean query per head. grid = HQ, block = HD threads (column-parallel)
// ---------------------------------------------------------------------------
__global__ void qmean_kernel()
{
    int h = blockIdx.x, d = threadIdx.x;
    const float* p = &g_qkv[h * HD + d];
    float s0 = 0.f, s1 = 0.f, s2 = 0.f, s3 = 0.f;
    float s4 = 0.f, s5 = 0.f, s6 = 0.f, s7 = 0.f;
    for (int i = 0; i < S; i += 8) {
        s0 += p[(size_t)(i + 0) * NQKV];
        s1 += p[(size_t)(i + 1) * NQKV];
        s2 += p[(size_t)(i + 2) * NQKV];
        s3 += p[(size_t)(i + 3) * NQKV];
        s4 += p[(size_t)(i + 4) * NQKV];
        s5 += p[(size_t)(i + 5) * NQKV];
        s6 += p[(size_t)(i + 6) * NQKV];
        s7 += p[(size_t)(i + 7) * NQKV];
    }
    g_qmean[h * HD + d] = (((s0 + s1) + (s2 + s3)) + ((s4 + s5) + (s6 + s7))) * (1.f / 4096.f);
}

// ---------------------------------------------------------------------------
// Scores + top-k block selection. One block per head, 512 threads (one per
// key-block). Sink/window masked to NEG before top-k; tie-break = lower index.
// ---------------------------------------------------------------------------
__global__ void scores_topk_kernel()
{
    __shared__ float qm[HD];
    __shared__ float sc[TB];
    __shared__ float rv[TB];
    __shared__ int   ri[TB];

    const int h  = blockIdx.x;
    const int t  = threadIdx.x;
    const int hl = h >> 2;

    if (t < HD) qm[t] = g_qmean[h * HD + t];
    __syncthreads();

    float s = 0.f;
    const float* kr = &g_krep[(t * HKV + hl) * HD];
#pragma unroll 8
    for (int d = 0; d < HD; ++d) s += qm[d] * kr[d];
    s *= SCALE;

    bool masked = (t < SINKB) || (t >= WINST);
    sc[t] = masked ? NEGF : s;

    if (t < 4) {
        g_blk[h * KLBLK + t]     = t;            // sink blocks 0..3
        g_blk[h * KLBLK + 4 + t] = WINST + t;    // window blocks 508..511
    }
    __syncthreads();

    for (int pick = 0; pick < MBTOP; ++pick) {
        rv[t] = sc[t];
        ri[t] = t;
        __syncthreads();
        for (int off = 256; off > 0; off >>= 1) {
            if (t < off) {
                float v2 = rv[t + off];
                int   i2 = ri[t + off];
                if (v2 > rv[t] || (v2 == rv[t] && i2 < ri[t])) { rv[t] = v2; ri[t] = i2; }
            }
            __syncthreads();
        }
        if (t == 0) {
            g_blk[h * KLBLK + 8 + pick] = ri[0];
            sc[ri[0]] = -2e30f;
        }
        __syncthreads();
    }
}

// ---------------------------------------------------------------------------
// Flash-style attention over the 864 selected tokens per head.
// grid = (S/64, HQ), 256 threads. Q tile 64 rows, key tile 32, online softmax.
// Tile-level skip when min selected token in tile > last query row (causal).
// ---------------------------------------------------------------------------
#define QT 64
#define KT 32
#define SMEM_ATTN 75652

__global__ __launch_bounds__(256)
void attn_kernel()
{
    extern __shared__ float sm[];
    float* Qs   = sm;                  // QT*129
    float* Kt   = Qs + QT * 129;       // 128*33  (d-major, transposed)
    float* Vs   = Kt + 128 * 33;       // KT*128
    float* Pp   = Vs + KT * 128;       // QT*33
    float* mrow = Pp + QT * 33;        // QT
    float* lrow = mrow + QT;           // QT
    float* crow = lrow + QT;           // QT
    int*   toks = (int*)(crow + QT);   // KT
    int*   sflg = toks + KT;           // 1

    const int tid = threadIdx.x;
    const int tx  = tid & 15;
    const int ty  = tid >> 4;
    const int h   = blockIdx.y;
    const int q0  = blockIdx.x * QT;
    const int hl  = h >> 2;

    // load Q tile (pre-scaled)
    for (int idx = tid; idx < QT * 32; idx += 256) {
        int r  = idx >> 5;
        int c4 = (idx & 31) << 2;
        float4 v = *(const float4*)&g_qkv[(size_t)(q0 + r) * NQKV + h * HD + c4];
        float* q = &Qs[r * 129 + c4];
        q[0] = v.x * SCALE; q[1] = v.y * SCALE; q[2] = v.z * SCALE; q[3] = v.w * SCALE;
    }
    if (tid < QT) { mrow[tid] = NEGF; lrow[tid] = 0.f; }

    float acc[4][8];
#pragma unroll
    for (int i = 0; i < 4; ++i)
#pragma unroll
        for (int j = 0; j < 8; ++j) acc[i][j] = 0.f;
    __syncthreads();

    for (int kt = 0; kt < KSEL / KT; ++kt) {
        if (tid < KT) {
            int j = kt * KT + tid;
            int b = g_blk[h * KLBLK + (j >> 3)];
            toks[tid] = (b << 3) + (j & 7);
        }
        __syncthreads();
        if (tid == 0) {
            int mn = toks[0];
#pragma unroll
            for (int i = 1; i < KT; ++i) mn = min(mn, toks[i]);
            sflg[0] = (mn > q0 + QT - 1);
        }
        __syncthreads();
        if (sflg[0]) continue;   // uniform branch

        // load K (transposed) + V tiles
        for (int idx = tid; idx < KT * 32; idx += 256) {
            int kj = idx >> 5;
            int c4 = (idx & 31) << 2;
            const float* kp = &g_qkv[(size_t)toks[kj] * NQKV + HQ * HD + hl * HD];
            float4 kv = *(const float4*)(kp + c4);
            Kt[(c4 + 0) * 33 + kj] = kv.x;
            Kt[(c4 + 1) * 33 + kj] = kv.y;
            Kt[(c4 + 2) * 33 + kj] = kv.z;
            Kt[(c4 + 3) * 33 + kj] = kv.w;
            float4 vv = *(const float4*)(kp + HKV * HD + c4);
            *(float4*)&Vs[kj * 128 + c4] = vv;
        }
        __syncthreads();

        // scores: 4 q-rows x 2 keys per thread
        float sr[4][2];
#pragma unroll
        for (int i = 0; i < 4; ++i) { sr[i][0] = 0.f; sr[i][1] = 0.f; }
#pragma unroll 4
        for (int d = 0; d < HD; ++d) {
            float b0 = Kt[d * 33 + (tx << 1)];
            float b1 = Kt[d * 33 + (tx << 1) + 1];
#pragma unroll
            for (int i = 0; i < 4; ++i) {
                float a = Qs[(ty * 4 + i) * 129 + d];
                sr[i][0] += a * b0;
                sr[i][1] += a * b1;
            }
        }
        // causal mask + write P
#pragma unroll
        for (int i = 0; i < 4; ++i) {
            int sq = q0 + ty * 4 + i;
#pragma unroll
            for (int j = 0; j < 2; ++j) {
                int tk = toks[(tx << 1) + j];
                Pp[(ty * 4 + i) * 33 + (tx << 1) + j] = (tk <= sq) ? sr[i][j] : NEGF;
            }
        }
        __syncthreads();

        // online softmax row update (one thread per row)
        if (tid < QT) {
            float mo = mrow[tid];
            float mt = mo;
#pragma unroll 8
            for (int j = 0; j < KT; ++j) mt = fmaxf(mt, Pp[tid * 33 + j]);
            float cc = __expf(mo - mt);     // mo==mt==NEG -> 1, l stays 0
            float ls = 0.f;
#pragma unroll 4
            for (int j = 0; j < KT; ++j) {
                float pv = Pp[tid * 33 + j];
                float e  = (pv > -1e29f) ? __expf(pv - mt) : 0.f;
                Pp[tid * 33 + j] = e;
                ls += e;
            }
            lrow[tid] = lrow[tid] * cc + ls;
            mrow[tid] = mt;
            crow[tid] = cc;
        }
        __syncthreads();

        // O update: 4 rows x 8 cols per thread
        float cc4[4];
#pragma unroll
        for (int i = 0; i < 4; ++i) cc4[i] = crow[ty * 4 + i];
#pragma unroll
        for (int i = 0; i < 4; ++i)
#pragma unroll
            for (int j = 0; j < 8; ++j) acc[i][j] *= cc4[i];

        for (int kj = 0; kj < KT; ++kj) {
            float4 v0 = *(const float4*)&Vs[kj * 128 + (tx << 3)];
            float4 v1 = *(const float4*)&Vs[kj * 128 + (tx << 3) + 4];
#pragma unroll
            for (int i = 0; i < 4; ++i) {
                float p = Pp[(ty * 4 + i) * 33 + kj];
                acc[i][0] += p * v0.x; acc[i][1] += p * v0.y;
                acc[i][2] += p * v0.z; acc[i][3] += p * v0.w;
                acc[i][4] += p * v1.x; acc[i][5] += p * v1.y;
                acc[i][6] += p * v1.z; acc[i][7] += p * v1.w;
            }
        }
    }

    // writeout
#pragma unroll
    for (int i = 0; i < 4; ++i) {
        float inv = 1.f / lrow[ty * 4 + i];
        float* op = &g_attn[(size_t)(q0 + ty * 4 + i) * DIMM + h * HD + (tx << 3)];
        float4 o0 = make_float4(acc[i][0] * inv, acc[i][1] * inv, acc[i][2] * inv, acc[i][3] * inv);
        float4 o1 = make_float4(acc[i][4] * inv, acc[i][5] * inv, acc[i][6] * inv, acc[i][7] * inv);
        *(float4*)op       = o0;
        *(float4*)(op + 4) = o1;
    }
}

// ---------------------------------------------------------------------------
// Host launcher
// ---------------------------------------------------------------------------
extern "C" void kernel_launch(void* const* d_in, const int* in_sizes, int n_in,
                              void* d_out, int out_size)
{
    (void)in_sizes; (void)n_in; (void)out_size;
    const float* x    = (const float*)d_in[0];   // (1, S, DIM)
    const float* fc   = (const float*)d_in[1];   // (S, 64, 2)
    const float* wqkv = (const float*)d_in[2];   // (6144, 4096)
    const float* wo   = (const float*)d_in[3];   // (4096, 4096)
    // d_in[4] = input_pos (arange, implied)
    float* y = (float*)d_out;                    // (1, S, DIM)

    float* qkv_p  = nullptr;
    float* attn_p = nullptr;
    cudaGetSymbolAddress((void**)&qkv_p,  g_qkv);
    cudaGetSymbolAddress((void**)&attn_p, g_attn);
    cudaFuncSetAttribute(attn_kernel, cudaFuncAttributeMaxDynamicSharedMemorySize, SMEM_ATTN);

    // 1. QKV projection: (4096 x 4096) @ (6144 x 4096)^T
    sgemm_nt<<<dim3(NQKV / 128, S / 128), 256>>>(x, wqkv, qkv_p, S, NQKV, DIMM);

    // 2. RoPE on q and k (in place)
    {
        int total = S * 40 * 64;
        rope_kernel<<<(total + 255) / 256, 256>>>(fc);
    }

    // 3. per-block key means + query mean
    kmean_kernel<<<(TB * HKV * HD) / 256, 256>>>();
    qmean_kernel<<<HQ, HD>>>();

    // 4. scores + top-k block selection
    scores_topk_kernel<<<HQ, TB>>>();

    // 5. sparse causal attention
    attn_kernel<<<dim3(S / QT, HQ), 256, SMEM_ATTN>>>();

    // 6. output projection: (4096 x 4096) @ (4096 x 4096)^T
    sgemm_nt<<<dim3(DIMM / 128, S / 128), 256>>>(attn_p, wo, y, S, DIMM, DIMM);
}

// round 3
// speedup vs baseline: 1.7645x; 1.7645x over previous
#include <cuda_runtime.h>
#include <cuda_bf16.h>
#include <cstdint>

// ---------------------------------------------------------------------------
// Problem constants (fixed shapes)
// ---------------------------------------------------------------------------
#define S      4096
#define DIMM   4096
#define HQ     32
#define HKV    8
#define HD     128
#define NQKV   6144          // (HQ + 2*HKV) * HD
#define TB     512           // S / 8 blocks
#define SINKB  4             // ceil(30/8)
#define WINST  508           // window start block
#define MBTOP  100           // heavy blocks
#define KLBLK  108           // 4 sink + 4 window + 100 heavy
#define KSEL   (KLBLK * 8)   // 864 selected tokens per head
#define NEGF   (-1e30f)
#define SCALE  0.08838834764831845f   // 1/sqrt(128)

// ---------------------------------------------------------------------------
// Scratch (static device globals — no runtime allocation allowed)
// ---------------------------------------------------------------------------
__device__ float g_qkv[(size_t)S * NQKV];     // qkv projections (q/k roped in-place)
__device__ float g_attn[(size_t)S * DIMM];    // attention output (S, H*D)
__device__ float g_krep[TB * HKV * HD];       // per-block mean keys
__device__ float g_qmean[HQ * HD];            // mean query per head
__device__ float g_qpart[16][HQ * HD];        // partial q sums (deterministic 2-stage)
__device__ int   g_blk[HQ * KLBLK];           // selected block ids per head

// ---------------------------------------------------------------------------
// mma.sync helpers (base-ISA tensor core path; NO tcgen05 on this toolchain)
// ---------------------------------------------------------------------------
__device__ __forceinline__ uint32_t smem_to_u32(const void* smem_ptr) {
    uint32_t addr;
    asm("{ .reg .u64 tmp; cvta.to.shared.u64 tmp, %1; cvt.u32.u64 %0, tmp; }"
        : "=r"(addr) : "l"(smem_ptr));
    return addr;
}

__device__ __forceinline__ void ldsm4(uint32_t* r, uint32_t addr) {
    asm volatile("ldmatrix.sync.aligned.m8n8.x4.shared.b16 {%0,%1,%2,%3}, [%4];"
        : "=r"(r[0]), "=r"(r[1]), "=r"(r[2]), "=r"(r[3]) : "r"(addr));
}

__device__ __forceinline__ void mma_bf16(float* d, const uint32_t* a, const uint32_t* b) {
    asm volatile("mma.sync.aligned.m16n8k16.row.col.f32.bf16.bf16.f32 "
        "{%0,%1,%2,%3}, {%4,%5,%6,%7}, {%8,%9}, {%0,%1,%2,%3};"
        : "+f"(d[0]), "+f"(d[1]), "+f"(d[2]), "+f"(d[3])
        : "r"(a[0]), "r"(a[1]), "r"(a[2]), "r"(a[3]), "r"(b[0]), "r"(b[1]));
}

// fp32 -> bf16 hi/lo split, 4 elems, packed 8-byte stores
__device__ __forceinline__ void cvt_store(float4 v, char* hi, char* lo) {
    __nv_bfloat16 h0 = __float2bfloat16(v.x);
    __nv_bfloat16 h1 = __float2bfloat16(v.y);
    __nv_bfloat16 h2 = __float2bfloat16(v.z);
    __nv_bfloat16 h3 = __float2bfloat16(v.w);
    __nv_bfloat16 l0 = __float2bfloat16(v.x - __bfloat162float(h0));
    __nv_bfloat16 l1 = __float2bfloat16(v.y - __bfloat162float(h1));
    __nv_bfloat16 l2 = __float2bfloat16(v.z - __bfloat162float(h2));
    __nv_bfloat16 l3 = __float2bfloat16(v.w - __bfloat162float(h3));
    uint2 hu, lu;
    hu.x = ((uint32_t)__bfloat16_as_ushort(h1) << 16) | __bfloat16_as_ushort(h0);
    hu.y = ((uint32_t)__bfloat16_as_ushort(h3) << 16) | __bfloat16_as_ushort(h2);
    lu.x = ((uint32_t)__bfloat16_as_ushort(l1) << 16) | __bfloat16_as_ushort(l0);
    lu.y = ((uint32_t)__bfloat16_as_ushort(l3) << 16) | __bfloat16_as_ushort(l2);
    *(uint2*)hi = hu;
    *(uint2*)lo = lu;
}

// ---------------------------------------------------------------------------
// Tensor-core GEMM:  C[M,N] = A[M,K] @ B[N,K]^T  (fp32 in/out, bf16x3 inside)
// 128x128 tile, BK=32, 256 threads (8 warps of 64x32), double-buffered smem.
// smem rows padded to 40 bf16 (80 B = odd*16B -> conflict-free ldmatrix).
// ---------------------------------------------------------------------------
#define LDS_ROW 40                      // bf16 elems per smem row (80 bytes)
#define TILE_BYTES (128 * LDS_ROW * 2)  // 10240 per matrix variant
#define AHI_OFF 0
#define ALO_OFF (TILE_BYTES)
#define BHI_OFF (2 * TILE_BYTES)
#define BLO_OFF (3 * TILE_BYTES)
#define GBUF_BYTES (4 * TILE_BYTES)     // 40960
#define SMEM_GEMM (2 * GBUF_BYTES)      // 81920

__global__ __launch_bounds__(256, 1)
void gemm_mma(const float* __restrict__ A, const float* __restrict__ B,
              float* __restrict__ C, int N, int K)
{
    extern __shared__ char smc[];
    const uint32_t sbase = smem_to_u32(smc);
    const int tid  = threadIdx.x;
    const int lane = tid & 31;
    const int wid  = tid >> 5;
    const int wm0  = (wid >> 2) << 6;   // 0 / 64
    const int wn0  = (wid & 3) << 5;    // 0/32/64/96
    const int bm   = blockIdx.y << 7;
    const int bn   = blockIdx.x << 7;

    float acc[4][4][4];
#pragma unroll
    for (int i = 0; i < 4; ++i)
#pragma unroll
        for (int j = 0; j < 4; ++j)
#pragma unroll
            for (int q = 0; q < 4; ++q) acc[i][j][q] = 0.f;

    // per-thread global load coords (4 float4 each for A and B per chunk)
    // u = tid + 256*i : row = u>>3 (0..127), col4 = (u&7)*4
    const int nch = K >> 5;

    // ldmatrix address components
    const int a_row = lane & 15;
    const int a_col8 = (lane >> 4) << 3;          // 0 or 8
    const int b_row = (lane & 7) + (((lane >> 4) & 1) << 3);
    const int b_col8 = ((lane >> 3) & 1) << 3;    // 0 or 8

    float4 pa[4], pb[4];

    // prologue: load + store chunk 0
#pragma unroll
    for (int i = 0; i < 4; ++i) {
        int u = tid + (i << 8);
        pa[i] = *(const float4*)(A + (size_t)(bm + (u >> 3)) * K + ((u & 7) << 2));
        pb[i] = *(const float4*)(B + (size_t)(bn + (u >> 3)) * K + ((u & 7) << 2));
    }
#pragma unroll
    for (int i = 0; i < 4; ++i) {
        int u = tid + (i << 8);
        uint32_t off = (u >> 3) * (LDS_ROW * 2) + ((u & 7) << 3);
        cvt_store(pa[i], smc + AHI_OFF + off, smc + ALO_OFF + off);
        cvt_store(pb[i], smc + BHI_OFF + off, smc + BLO_OFF + off);
    }
    __syncthreads();

    for (int c = 0; c < nch; ++c) {
        const uint32_t boff = (c & 1) ? GBUF_BYTES : 0;

        if (c + 1 < nch) {
            const int kb = (c + 1) << 5;
#pragma unroll
            for (int i = 0; i < 4; ++i) {
                int u = tid + (i << 8);
                pa[i] = *(const float4*)(A + (size_t)(bm + (u >> 3)) * K + kb + ((u & 7) << 2));
                pb[i] = *(const float4*)(B + (size_t)(bn + (u >> 3)) * K + kb + ((u & 7) << 2));
            }
        }

        // 2 k16 steps in this chunk
#pragma unroll
        for (int ks = 0; ks < 2; ++ks) {
            uint32_t ahi[4][4], alo[4][4], bhi[2][4], blo[2][4];
            const int kc = (ks << 4);
#pragma unroll
            for (int mt = 0; mt < 4; ++mt) {
                uint32_t off = (uint32_t)(wm0 + (mt << 4) + a_row) * (LDS_ROW * 2)
                             + (uint32_t)(kc + a_col8) * 2;
                ldsm4(ahi[mt], sbase + boff + AHI_OFF + off);
                ldsm4(alo[mt], sbase + boff + ALO_OFF + off);
            }
#pragma unroll
            for (int np = 0; np < 2; ++np) {
                uint32_t off = (uint32_t)(wn0 + (np << 4) + b_row) * (LDS_ROW * 2)
                             + (uint32_t)(kc + b_col8) * 2;
                ldsm4(bhi[np], sbase + boff + BHI_OFF + off);
                ldsm4(blo[np], sbase + boff + BLO_OFF + off);
            }
#pragma unroll
            for (int mt = 0; mt < 4; ++mt) {
#pragma unroll
                for (int nt = 0; nt < 4; ++nt) {
                    const uint32_t* bh = &bhi[nt >> 1][(nt & 1) << 1];
                    const uint32_t* bl = &blo[nt >> 1][(nt & 1) << 1];
                    mma_bf16(acc[mt][nt], ahi[mt], bh);
                    mma_bf16(acc[mt][nt], ahi[mt], bl);
                    mma_bf16(acc[mt][nt], alo[mt], bh);
                }
            }
        }

        __syncthreads();
        if (c + 1 < nch) {
            const uint32_t nb = ((c + 1) & 1) ? GBUF_BYTES : 0;
#pragma unroll
            for (int i = 0; i < 4; ++i) {
                int u = tid + (i << 8);
                uint32_t off = (u >> 3) * (LDS_ROW * 2) + ((u & 7) << 3);
                cvt_store(pa[i], smc + nb + AHI_OFF + off, smc + nb + ALO_OFF + off);
                cvt_store(pb[i], smc + nb + BHI_OFF + off, smc + nb + BLO_OFF + off);
            }
            __syncthreads();
        }
    }

    // epilogue: accum fragments -> C
    const int er = lane >> 2;
    const int ec = (lane & 3) << 1;
#pragma unroll
    for (int mt = 0; mt < 4; ++mt) {
#pragma unroll
        for (int nt = 0; nt < 4; ++nt) {
            int r0 = bm + wm0 + (mt << 4) + er;
            int c0 = bn + wn0 + (nt << 3) + ec;
            *(float2*)(C + (size_t)r0 * N + c0)       = make_float2(acc[mt][nt][0], acc[mt][nt][1]);
            *(float2*)(C + (size_t)(r0 + 8) * N + c0) = make_float2(acc[mt][nt][2], acc[mt][nt][3]);
        }
    }
}

// ---------------------------------------------------------------------------
// RoPE in-place on q and k slices of g_qkv. one thread per (s, head40, pair)
// ---------------------------------------------------------------------------
__global__ void rope_kernel(const float* __restrict__ fc)
{
    const int total = S * 40 * 64;
    int tid = blockIdx.x * blockDim.x + threadIdx.x;
    if (tid >= total) return;
    int j  = tid & 63;
    int r  = tid >> 6;
    int hh = r % 40;          // 0..31 = q heads, 32..39 = k heads
    int s  = r / 40;
    float* p = &g_qkv[(size_t)s * NQKV + hh * HD + (j << 1)];
    float f0 = fc[s * HD + (j << 1)];
    float f1 = fc[s * HD + (j << 1) + 1];
    float x0 = p[0], x1 = p[1];
    p[0] = x0 * f0 - x1 * f1;
    p[1] = x1 * f0 + x0 * f1;
}

// ---------------------------------------------------------------------------
// Per-block key means (8 tokens per block)
// ---------------------------------------------------------------------------
__global__ void kmean_kernel()
{
    int idx = blockIdx.x * blockDim.x + threadIdx.x;   // TB*HKV*HD threads
    int d  = idx & 127;
    int hl = (idx >> 7) & 7;
    int t  = idx >> 10;
    const float* p = &g_qkv[(size_t)(t * 8) * NQKV + HQ * HD + hl * HD + d];
    float s = 0.f;
#pragma unroll
    for (int i = 0; i < 8; ++i) s += p[(size_t)i * NQKV];
    g_krep[idx] = s * 0.125f;
}

// ---------------------------------------------------------------------------
// Mean query per head — deterministic 2-stage
// ---------------------------------------------------------------------------
__global__ void qmean_part_kernel()   // grid (HQ, 16), 128 threads
{
    int h = blockIdx.x, chunk = blockIdx.y, d = threadIdx.x;
    const float* p = &g_qkv[(size_t)(chunk * 256) * NQKV + h * HD + d];
    float s = 0.f;
#pragma unroll 4
    for (int i = 0; i < 256; ++i) s += p[(size_t)i * NQKV];
    g_qpart[chunk][h * HD + d] = s;
}

__global__ void qmean_final_kernel()  // HQ*HD threads total
{
    int idx = blockIdx.x * blockDim.x + threadIdx.x;
    float s = 0.f;
#pragma unroll
    for (int i = 0; i < 16; ++i) s += g_qpart[i][idx];
    g_qmean[idx] = s * (1.f / 4096.f);
}

// ---------------------------------------------------------------------------
// Scores + top-k block selection. One block per head, 512 threads.
// ---------------------------------------------------------------------------
__global__ void scores_topk_kernel()
{
    __shared__ float qm[HD];
    __shared__ float sc[TB];
    __shared__ float rv[TB];
    __shared__ int   ri[TB];

    const int h  = blockIdx.x;
    const int t  = threadIdx.x;
    const int hl = h >> 2;

    if (t < HD) qm[t] = g_qmean[h * HD + t];
    __syncthreads();

    float s = 0.f;
    const float* kr = &g_krep[(t * HKV + hl) * HD];
#pragma unroll 8
    for (int d = 0; d < HD; ++d) s += qm[d] * kr[d];
    s *= SCALE;

    bool masked = (t < SINKB) || (t >= WINST);
    sc[t] = masked ? NEGF : s;

    if (t < 4) {
        g_blk[h * KLBLK + t]     = t;            // sink blocks 0..3
        g_blk[h * KLBLK + 4 + t] = WINST + t;    // window blocks 508..511
    }
    __syncthreads();

    for (int pick = 0; pick < MBTOP; ++pick) {
        rv[t] = sc[t];
        ri[t] = t;
        __syncthreads();
        for (int off = 256; off > 0; off >>= 1) {
            if (t < off) {
                float v2 = rv[t + off];
                int   i2 = ri[t + off];
                if (v2 > rv[t] || (v2 == rv[t] && i2 < ri[t])) { rv[t] = v2; ri[t] = i2; }
            }
            __syncthreads();
        }
        if (t == 0) {
            g_blk[h * KLBLK + 8 + pick] = ri[0];
            sc[ri[0]] = -2e30f;
        }
        __syncthreads();
    }
}

// ---------------------------------------------------------------------------
// Flash-style attention over the 864 selected tokens per head.
// grid = (S/64, HQ), 256 threads. Q tile 64 rows, key tile 32, online softmax.
// ---------------------------------------------------------------------------
#define QT 64
#define KT 32
#define SMEM_ATTN 75652

__global__ __launch_bounds__(256)
void attn_kernel()
{
    extern __shared__ float smf[];
    float* Qs   = smf;                 // QT*129
    float* Kt   = Qs + QT * 129;       // 128*33  (d-major, transposed)
    float* Vs   = Kt + 128 * 33;       // KT*128
    float* Pp   = Vs + KT * 128;       // QT*33
    float* mrow = Pp + QT * 33;        // QT
    float* lrow = mrow + QT;           // QT
    float* crow = lrow + QT;           // QT
    int*   toks = (int*)(crow + QT);   // KT
    int*   sflg = toks + KT;           // 1

    const int tid = threadIdx.x;
    const int tx  = tid & 15;
    const int ty  = tid >> 4;
    const int h   = blockIdx.y;
    const int q0  = blockIdx.x * QT;
    const int hl  = h >> 2;

    for (int idx = tid; idx < QT * 32; idx += 256) {
        int r  = idx >> 5;
        int c4 = (idx & 31) << 2;
        float4 v = *(const float4*)&g_qkv[(size_t)(q0 + r) * NQKV + h * HD + c4];
        float* q = &Qs[r * 129 + c4];
        q[0] = v.x * SCALE; q[1] = v.y * SCALE; q[2] = v.z * SCALE; q[3] = v.w * SCALE;
    }
    if (tid < QT) { mrow[tid] = NEGF; lrow[tid] = 0.f; }

    float acc[4][8];
#pragma unroll
    for (int i = 0; i < 4; ++i)
#pragma unroll
        for (int j = 0; j < 8; ++j) acc[i][j] = 0.f;
    __syncthreads();

    for (int kt = 0; kt < KSEL / KT; ++kt) {
        if (tid < KT) {
            int j = kt * KT + tid;
            int b = g_blk[h * KLBLK + (j >> 3)];
            toks[tid] = (b << 3) + (j & 7);
        }
        __syncthreads();
        if (tid == 0) {
            int mn = toks[0];
#pragma unroll
            for (int i = 1; i < KT; ++i) mn = min(mn, toks[i]);
            sflg[0] = (mn > q0 + QT - 1);
        }
        __syncthreads();
        if (sflg[0]) continue;   // uniform branch

        for (int idx = tid; idx < KT * 32; idx += 256) {
            int kj = idx >> 5;
            int c4 = (idx & 31) << 2;
            const float* kp = &g_qkv[(size_t)toks[kj] * NQKV + HQ * HD + hl * HD];
            float4 kv = *(const float4*)(kp + c4);
            Kt[(c4 + 0) * 33 + kj] = kv.x;
            Kt[(c4 + 1) * 33 + kj] = kv.y;
            Kt[(c4 + 2) * 33 + kj] = kv.z;
            Kt[(c4 + 3) * 33 + kj] = kv.w;
            float4 vv = *(const float4*)(kp + HKV * HD + c4);
            *(float4*)&Vs[kj * 128 + c4] = vv;
        }
        __syncthreads();

        float sr[4][2];
#pragma unroll
        for (int i = 0; i < 4; ++i) { sr[i][0] = 0.f; sr[i][1] = 0.f; }
#pragma unroll 4
        for (int d = 0; d < HD; ++d) {
            float b0 = Kt[d * 33 + (tx << 1)];
            float b1 = Kt[d * 33 + (tx << 1) + 1];
#pragma unroll
            for (int i = 0; i < 4; ++i) {
                float a = Qs[(ty * 4 + i) * 129 + d];
                sr[i][0] += a * b0;
                sr[i][1] += a * b1;
            }
        }
#pragma unroll
        for (int i = 0; i < 4; ++i) {
            int sq = q0 + ty * 4 + i;
#pragma unroll
            for (int j = 0; j < 2; ++j) {
                int tk = toks[(tx << 1) + j];
                Pp[(ty * 4 + i) * 33 + (tx << 1) + j] = (tk <= sq) ? sr[i][j] : NEGF;
            }
        }
        __syncthreads();

        if (tid < QT) {
            float mo = mrow[tid];
            float mt = mo;
#pragma unroll 8
            for (int j = 0; j < KT; ++j) mt = fmaxf(mt, Pp[tid * 33 + j]);
            float cc = __expf(mo - mt);
            float ls = 0.f;
#pragma unroll 4
            for (int j = 0; j < KT; ++j) {
                float pv = Pp[tid * 33 + j];
                float e  = (pv > -1e29f) ? __expf(pv - mt) : 0.f;
                Pp[tid * 33 + j] = e;
                ls += e;
            }
            lrow[tid] = lrow[tid] * cc + ls;
            mrow[tid] = mt;
            crow[tid] = cc;
        }
        __syncthreads();

        float cc4[4];
#pragma unroll
        for (int i = 0; i < 4; ++i) cc4[i] = crow[ty * 4 + i];
#pragma unroll
        for (int i = 0; i < 4; ++i)
#pragma unroll
            for (int j = 0; j < 8; ++j) acc[i][j] *= cc4[i];

        for (int kj = 0; kj < KT; ++kj) {
            float4 v0 = *(const float4*)&Vs[kj * 128 + (tx << 3)];
            float4 v1 = *(const float4*)&Vs[kj * 128 + (tx << 3) + 4];
#pragma unroll
            for (int i = 0; i < 4; ++i) {
                float p = Pp[(ty * 4 + i) * 33 + kj];
                acc[i][0] += p * v0.x; acc[i][1] += p * v0.y;
                acc[i][2] += p * v0.z; acc[i][3] += p * v0.w;
                acc[i][4] += p * v1.x; acc[i][5] += p * v1.y;
                acc[i][6] += p * v1.z; acc[i][7] += p * v1.w;
            }
        }
    }

#pragma unroll
    for (int i = 0; i < 4; ++i) {
        float inv = 1.f / lrow[ty * 4 + i];
        float* op = &g_attn[(size_t)(q0 + ty * 4 + i) * DIMM + h * HD + (tx << 3)];
        float4 o0 = make_float4(acc[i][0] * inv, acc[i][1] * inv, acc[i][2] * inv, acc[i][3] * inv);
        float4 o1 = make_float4(acc[i][4] * inv, acc[i][5] * inv, acc[i][6] * inv, acc[i][7] * inv);
        *(float4*)op       = o0;
        *(float4*)(op + 4) = o1;
    }
}

// ---------------------------------------------------------------------------
// Host launcher
// ---------------------------------------------------------------------------
extern "C" void kernel_launch(void* const* d_in, const int* in_sizes, int n_in,
                              void* d_out, int out_size)
{
    (void)in_sizes; (void)n_in; (void)out_size;
    const float* x    = (const float*)d_in[0];   // (1, S, DIM)
    const float* fc   = (const float*)d_in[1];   // (S, 64, 2)
    const float* wqkv = (const float*)d_in[2];   // (6144, 4096)
    const float* wo   = (const float*)d_in[3];   // (4096, 4096)
    float* y = (float*)d_out;                    // (1, S, DIM)

    float* qkv_p  = nullptr;
    float* attn_p = nullptr;
    cudaGetSymbolAddress((void**)&qkv_p,  g_qkv);
    cudaGetSymbolAddress((void**)&attn_p, g_attn);
    cudaFuncSetAttribute(attn_kernel, cudaFuncAttributeMaxDynamicSharedMemorySize, SMEM_ATTN);
    cudaFuncSetAttribute(gemm_mma,    cudaFuncAttributeMaxDynamicSharedMemorySize, SMEM_GEMM);

    // 1. QKV projection: (4096 x 4096) @ (6144 x 4096)^T  -> bf16x3 mma.sync
    gemm_mma<<<dim3(NQKV / 128, S / 128), 256, SMEM_GEMM>>>(x, wqkv, qkv_p, NQKV, DIMM);

    // 2. RoPE on q and k (in place)
    {
        int total = S * 40 * 64;
        rope_kernel<<<(total + 255) / 256, 256>>>(fc);
    }

    // 3. per-block key means + query mean (2-stage deterministic)
    kmean_kernel<<<(TB * HKV * HD) / 256, 256>>>();
    qmean_part_kernel<<<dim3(HQ, 16), 128>>>();
    qmean_final_kernel<<<(HQ * HD) / 128, 128>>>();

    // 4. scores + top-k block selection
    scores_topk_kernel<<<HQ, TB>>>();

    // 5. sparse causal attention
    attn_kernel<<<dim3(S / QT, HQ), 256, SMEM_ATTN>>>();

    // 6. output projection: (4096 x 4096) @ (4096 x 4096)^T -> bf16x3 mma.sync
    gemm_mma<<<dim3(DIMM / 128, S / 128), 256, SMEM_GEMM>>>(attn_p, wo, y, DIMM, DIMM);
}

// round 4
// speedup vs baseline: 1.8691x; 1.0593x over previous
#include <cuda_runtime.h>
#include <cuda_bf16.h>
#include <cstdint>

// ---------------------------------------------------------------------------
// Problem constants (fixed shapes)
// ---------------------------------------------------------------------------
#define S      4096
#define DIMM   4096
#define HQ     32
#define HKV    8
#define HD     128
#define NQKV   6144          // (HQ + 2*HKV) * HD
#define TB     512           // S / 8 blocks
#define SINKB  4             // ceil(30/8)
#define WINST  508           // window start block
#define MBTOP  100           // heavy blocks
#define KLBLK  108           // 4 sink + 4 window + 100 heavy
#define KSEL   (KLBLK * 8)   // 864 selected tokens per head
#define NEGF   (-1e30f)
#define SCALE  0.08838834764831845f   // 1/sqrt(128)

// ---------------------------------------------------------------------------
// Scratch (static device globals — no runtime allocation allowed)
// ---------------------------------------------------------------------------
__device__ float g_qkv[(size_t)S * NQKV];     // qkv projections (q/k roped in-place)
__device__ float g_krep[TB * HKV * HD];       // per-block mean keys
__device__ float g_qmean[HQ * HD];            // mean query per head
__device__ float g_qpart[16][HQ * HD];        // partial q sums (deterministic 2-stage)
__device__ int   g_blk[HQ * KLBLK];           // selected block ids per head

// bf16 hi/lo split operands for the tensor-core GEMMs
__device__ __nv_bfloat16 g_xh[(size_t)S * DIMM];
__device__ __nv_bfloat16 g_xl[(size_t)S * DIMM];
__device__ __nv_bfloat16 g_wqh[(size_t)NQKV * DIMM];
__device__ __nv_bfloat16 g_wql[(size_t)NQKV * DIMM];
__device__ __nv_bfloat16 g_woh[(size_t)DIMM * DIMM];
__device__ __nv_bfloat16 g_wol[(size_t)DIMM * DIMM];
__device__ __nv_bfloat16 g_ath[(size_t)S * DIMM];   // attention out hi
__device__ __nv_bfloat16 g_atl[(size_t)S * DIMM];   // attention out lo

// ---------------------------------------------------------------------------
// asm helpers (base-ISA only; no tcgen05 on this toolchain)
// ---------------------------------------------------------------------------
__device__ __forceinline__ uint32_t smem_to_u32(const void* smem_ptr) {
    uint32_t addr;
    asm("{ .reg .u64 tmp; cvta.to.shared.u64 tmp, %1; cvt.u32.u64 %0, tmp; }"
        : "=r"(addr) : "l"(smem_ptr));
    return addr;
}

__device__ __forceinline__ void ldsm4(uint32_t* r, uint32_t addr) {
    asm volatile("ldmatrix.sync.aligned.m8n8.x4.shared.b16 {%0,%1,%2,%3}, [%4];"
        : "=r"(r[0]), "=r"(r[1]), "=r"(r[2]), "=r"(r[3]) : "r"(addr));
}

__device__ __forceinline__ void mma_bf16(float* d, const uint32_t* a, const uint32_t* b) {
    asm volatile("mma.sync.aligned.m16n8k16.row.col.f32.bf16.bf16.f32 "
        "{%0,%1,%2,%3}, {%4,%5,%6,%7}, {%8,%9}, {%0,%1,%2,%3};"
        : "+f"(d[0]), "+f"(d[1]), "+f"(d[2]), "+f"(d[3])
        : "r"(a[0]), "r"(a[1]), "r"(a[2]), "r"(a[3]), "r"(b[0]), "r"(b[1]));
}

#define CP16(dst, src) \
    asm volatile("cp.async.cg.shared.global [%0], [%1], 16;" :: "r"(dst), "l"(src))
#define CP_COMMIT() asm volatile("cp.async.commit_group;" ::: "memory")
#define CP_WAIT(n)  asm volatile("cp.async.wait_group %0;" :: "n"(n) : "memory")

// ---------------------------------------------------------------------------
// fp32 -> bf16 hi/lo split (pre-pass), float4 per thread
// ---------------------------------------------------------------------------
__global__ void split_kernel(const float* __restrict__ in,
                             __nv_bfloat16* __restrict__ hi,
                             __nv_bfloat16* __restrict__ lo, int n4)
{
    int i = blockIdx.x * blockDim.x + threadIdx.x;
    if (i >= n4) return;
    float4 v = ((const float4*)in)[i];
    __nv_bfloat16 h0 = __float2bfloat16(v.x);
    __nv_bfloat16 h1 = __float2bfloat16(v.y);
    __nv_bfloat16 h2 = __float2bfloat16(v.z);
    __nv_bfloat16 h3 = __float2bfloat16(v.w);
    __nv_bfloat16 l0 = __float2bfloat16(v.x - __bfloat162float(h0));
    __nv_bfloat16 l1 = __float2bfloat16(v.y - __bfloat162float(h1));
    __nv_bfloat16 l2 = __float2bfloat16(v.z - __bfloat162float(h2));
    __nv_bfloat16 l3 = __float2bfloat16(v.w - __bfloat162float(h3));
    uint2 H, L;
    H.x = ((uint32_t)__bfloat16_as_ushort(h1) << 16) | __bfloat16_as_ushort(h0);
    H.y = ((uint32_t)__bfloat16_as_ushort(h3) << 16) | __bfloat16_as_ushort(h2);
    L.x = ((uint32_t)__bfloat16_as_ushort(l1) << 16) | __bfloat16_as_ushort(l0);
    L.y = ((uint32_t)__bfloat16_as_ushort(l3) << 16) | __bfloat16_as_ushort(l2);
    ((uint2*)hi)[i] = H;
    ((uint2*)lo)[i] = L;
}

// ---------------------------------------------------------------------------
// Tensor-core GEMM:  C[M,N] = (Ah+Al)[M,K] @ (Bh+Bl)[N,K]^T  (bf16x3, fp32 acc)
// 128x128 tile, BK=32, 256 threads (8 warps of 64x32), cp.async double buffer.
// smem rows padded to 40 bf16 (80 B = odd*16B -> conflict-free ldmatrix).
// ---------------------------------------------------------------------------
#define LDS_ROW 40                      // bf16 elems per smem row (80 bytes)
#define TILE_BYTES (128 * LDS_ROW * 2)  // 10240 per matrix variant
#define AHI_OFF 0
#define ALO_OFF (TILE_BYTES)
#define BHI_OFF (2 * TILE_BYTES)
#define BLO_OFF (3 * TILE_BYTES)
#define GBUF_BYTES (4 * TILE_BYTES)     // 40960
#define SMEM_GEMM (2 * GBUF_BYTES)      // 81920

// issue one 32-K chunk of cp.async copies into buffer at byte offset `boff`
#define GEMM_ISSUE(cc, boff) do {                                              \
    const int kb_ = (cc) << 5;                                                 \
    _Pragma("unroll")                                                          \
    for (int i_ = 0; i_ < 2; ++i_) {                                           \
        int u_   = tid + (i_ << 8);                                            \
        int row_ = u_ >> 2;                                                    \
        int seg_ = (u_ & 3) << 3;   /* bf16 elem offset: 0,8,16,24 */          \
        uint32_t d_ = sbase + (boff) +                                         \
                      (uint32_t)(row_ * (LDS_ROW * 2) + (seg_ << 1));          \
        CP16(d_ + AHI_OFF, Ah + (size_t)(bm + row_) * K + kb_ + seg_);         \
        CP16(d_ + ALO_OFF, Al + (size_t)(bm + row_) * K + kb_ + seg_);         \
        CP16(d_ + BHI_OFF, Bh + (size_t)(bn + row_) * K + kb_ + seg_);         \
        CP16(d_ + BLO_OFF, Bl + (size_t)(bn + row_) * K + kb_ + seg_);         \
    }                                                                          \
} while (0)

__global__ __launch_bounds__(256, 1)
void gemm_bf16(const __nv_bfloat16* __restrict__ Ah, const __nv_bfloat16* __restrict__ Al,
               const __nv_bfloat16* __restrict__ Bh, const __nv_bfloat16* __restrict__ Bl,
               float* __restrict__ C, int N, int K)
{
    extern __shared__ char smc[];
    const uint32_t sbase = smem_to_u32(smc);
    const int tid  = threadIdx.x;
    const int lane = tid & 31;
    const int wid  = tid >> 5;
    const int wm0  = (wid >> 2) << 6;   // 0 / 64
    const int wn0  = (wid & 3) << 5;    // 0/32/64/96
    const int bm   = blockIdx.y << 7;
    const int bn   = blockIdx.x << 7;

    float acc[4][4][4];
#pragma unroll
    for (int i = 0; i < 4; ++i)
#pragma unroll
        for (int j = 0; j < 4; ++j)
#pragma unroll
            for (int q = 0; q < 4; ++q) acc[i][j][q] = 0.f;

    const int nch = K >> 5;

    // ldmatrix address components
    const int a_row  = lane & 15;
    const int a_col8 = (lane >> 4) << 3;          // 0 or 8
    const int b_row  = (lane & 7) + (((lane >> 4) & 1) << 3);
    const int b_col8 = ((lane >> 3) & 1) << 3;    // 0 or 8

    GEMM_ISSUE(0, 0u);
    CP_COMMIT();

    for (int c = 0; c < nch; ++c) {
        const uint32_t boff = (c & 1) ? GBUF_BYTES : 0;

        if (c + 1 < nch) {
            const uint32_t nb = ((c + 1) & 1) ? GBUF_BYTES : 0u;
            GEMM_ISSUE(c + 1, nb);
            CP_COMMIT();
            CP_WAIT(1);
        } else {
            CP_WAIT(0);
        }
        __syncthreads();

        // 2 k16 steps in this chunk
#pragma unroll
        for (int ks = 0; ks < 2; ++ks) {
            uint32_t ahi[4][4], alo[4][4], bhi[2][4], blo[2][4];
            const int kc = (ks << 4);
#pragma unroll
            for (int mt = 0; mt < 4; ++mt) {
                uint32_t off = (uint32_t)(wm0 + (mt << 4) + a_row) * (LDS_ROW * 2)
                             + (uint32_t)(kc + a_col8) * 2;
                ldsm4(ahi[mt], sbase + boff + AHI_OFF + off);
                ldsm4(alo[mt], sbase + boff + ALO_OFF + off);
            }
#pragma unroll
            for (int np = 0; np < 2; ++np) {
                uint32_t off = (uint32_t)(wn0 + (np << 4) + b_row) * (LDS_ROW * 2)
                             + (uint32_t)(kc + b_col8) * 2;
                ldsm4(bhi[np], sbase + boff + BHI_OFF + off);
                ldsm4(blo[np], sbase + boff + BLO_OFF + off);
            }
#pragma unroll
            for (int mt = 0; mt < 4; ++mt) {
#pragma unroll
                for (int nt = 0; nt < 4; ++nt) {
                    const uint32_t* bh = &bhi[nt >> 1][(nt & 1) << 1];
                    const uint32_t* bl = &blo[nt >> 1][(nt & 1) << 1];
                    mma_bf16(acc[mt][nt], ahi[mt], bh);
                    mma_bf16(acc[mt][nt], ahi[mt], bl);
                    mma_bf16(acc[mt][nt], alo[mt], bh);
                }
            }
        }
        __syncthreads();
    }

    // epilogue: accum fragments -> C
    const int er = lane >> 2;
    const int ec = (lane & 3) << 1;
#pragma unroll
    for (int mt = 0; mt < 4; ++mt) {
#pragma unroll
        for (int nt = 0; nt < 4; ++nt) {
            int r0 = bm + wm0 + (mt << 4) + er;
            int c0 = bn + wn0 + (nt << 3) + ec;
            *(float2*)(C + (size_t)r0 * N + c0)       = make_float2(acc[mt][nt][0], acc[mt][nt][1]);
            *(float2*)(C + (size_t)(r0 + 8) * N + c0) = make_float2(acc[mt][nt][2], acc[mt][nt][3]);
        }
    }
}

// ---------------------------------------------------------------------------
// RoPE in-place on q and k slices of g_qkv. one thread per (s, head40, pair)
// ---------------------------------------------------------------------------
__global__ void rope_kernel(const float* __restrict__ fc)
{
    const int total = S * 40 * 64;
    int tid = blockIdx.x * blockDim.x + threadIdx.x;
    if (tid >= total) return;
    int j  = tid & 63;
    int r  = tid >> 6;
    int hh = r % 40;          // 0..31 = q heads, 32..39 = k heads
    int s  = r / 40;
    float* p = &g_qkv[(size_t)s * NQKV + hh * HD + (j << 1)];
    float f0 = fc[s * HD + (j << 1)];
    float f1 = fc[s * HD + (j << 1) + 1];
    float x0 = p[0], x1 = p[1];
    p[0] = x0 * f0 - x1 * f1;
    p[1] = x1 * f0 + x0 * f1;
}

// ---------------------------------------------------------------------------
// Per-block key means (8 tokens per block)
// ---------------------------------------------------------------------------
__global__ void kmean_kernel()
{
    int idx = blockIdx.x * blockDim.x + threadIdx.x;   // TB*HKV*HD threads
    int d  = idx & 127;
    int hl = (idx >> 7) & 7;
    int t  = idx >> 10;
    const float* p = &g_qkv[(size_t)(t * 8) * NQKV + HQ * HD + hl * HD + d];
    float s = 0.f;
#pragma unroll
    for (int i = 0; i < 8; ++i) s += p[(size_t)i * NQKV];
    g_krep[idx] = s * 0.125f;
}

// ---------------------------------------------------------------------------
// Mean query per head — deterministic 2-stage
// ---------------------------------------------------------------------------
__global__ void qmean_part_kernel()   // grid (HQ, 16), 128 threads
{
    int h = blockIdx.x, chunk = blockIdx.y, d = threadIdx.x;
    const float* p = &g_qkv[(size_t)(chunk * 256) * NQKV + h * HD + d];
    float s = 0.f;
#pragma unroll 4
    for (int i = 0; i < 256; ++i) s += p[(size_t)i * NQKV];
    g_qpart[chunk][h * HD + d] = s;
}

__global__ void qmean_final_kernel()  // HQ*HD threads total
{
    int idx = blockIdx.x * blockDim.x + threadIdx.x;
    float s = 0.f;
#pragma unroll
    for (int i = 0; i < 16; ++i) s += g_qpart[i][idx];
    g_qmean[idx] = s * (1.f / 4096.f);
}

// ---------------------------------------------------------------------------
// Scores + top-k block selection. One block per head, 512 threads.
// ---------------------------------------------------------------------------
__global__ void scores_topk_kernel()
{
    __shared__ float qm[HD];
    __shared__ float sc[TB];
    __shared__ float rv[TB];
    __shared__ int   ri[TB];

    const int h  = blockIdx.x;
    const int t  = threadIdx.x;
    const int hl = h >> 2;

    if (t < HD) qm[t] = g_qmean[h * HD + t];
    __syncthreads();

    float s = 0.f;
    const float* kr = &g_krep[(t * HKV + hl) * HD];
#pragma unroll 8
    for (int d = 0; d < HD; ++d) s += qm[d] * kr[d];
    s *= SCALE;

    bool masked = (t < SINKB) || (t >= WINST);
    sc[t] = masked ? NEGF : s;

    if (t < 4) {
        g_blk[h * KLBLK + t]     = t;            // sink blocks 0..3
        g_blk[h * KLBLK + 4 + t] = WINST + t;    // window blocks 508..511
    }
    __syncthreads();

    for (int pick = 0; pick < MBTOP; ++pick) {
        rv[t] = sc[t];
        ri[t] = t;
        __syncthreads();
        for (int off = 256; off > 0; off >>= 1) {
            if (t < off) {
                float v2 = rv[t + off];
                int   i2 = ri[t + off];
                if (v2 > rv[t] || (v2 == rv[t] && i2 < ri[t])) { rv[t] = v2; ri[t] = i2; }
            }
            __syncthreads();
        }
        if (t == 0) {
            g_blk[h * KLBLK + 8 + pick] = ri[0];
            sc[ri[0]] = -2e30f;
        }
        __syncthreads();
    }
}

// ---------------------------------------------------------------------------
// Flash-style attention over the 864 selected tokens per head.
// grid = (S/64, HQ), 256 threads. Q tile 64 rows, key tile 32, online softmax.
// Output written directly as bf16 hi/lo (feeds the WO GEMM).
// ---------------------------------------------------------------------------
#define QT 64
#define KT 32
#define SMEM_ATTN 75652

__global__ __launch_bounds__(256)
void attn_kernel()
{
    extern __shared__ float smf[];
    float* Qs   = smf;                 // QT*129
    float* Kt   = Qs + QT * 129;       // 128*33  (d-major, transposed)
    float* Vs   = Kt + 128 * 33;       // KT*128
    float* Pp   = Vs + KT * 128;       // QT*33
    float* mrow = Pp + QT * 33;        // QT
    float* lrow = mrow + QT;           // QT
    float* crow = lrow + QT;           // QT
    int*   toks = (int*)(crow + QT);   // KT
    int*   sflg = toks + KT;           // 1

    const int tid = threadIdx.x;
    const int tx  = tid & 15;
    const int ty  = tid >> 4;
    const int h   = blockIdx.y;
    const int q0  = blockIdx.x * QT;
    const int hl  = h >> 2;

    for (int idx = tid; idx < QT * 32; idx += 256) {
        int r  = idx >> 5;
        int c4 = (idx & 31) << 2;
        float4 v = *(const float4*)&g_qkv[(size_t)(q0 + r) * NQKV + h * HD + c4];
        float* q = &Qs[r * 129 + c4];
        q[0] = v.x * SCALE; q[1] = v.y * SCALE; q[2] = v.z * SCALE; q[3] = v.w * SCALE;
    }
    if (tid < QT) { mrow[tid] = NEGF; lrow[tid] = 0.f; }

    float acc[4][8];
#pragma unroll
    for (int i = 0; i < 4; ++i)
#pragma unroll
        for (int j = 0; j < 8; ++j) acc[i][j] = 0.f;
    __syncthreads();

    for (int kt = 0; kt < KSEL / KT; ++kt) {
        if (tid < KT) {
            int j = kt * KT + tid;
            int b = g_blk[h * KLBLK + (j >> 3)];
            toks[tid] = (b << 3) + (j & 7);
        }
        __syncthreads();
        if (tid == 0) {
            int mn = toks[0];
#pragma unroll
            for (int i = 1; i < KT; ++i) mn = min(mn, toks[i]);
            sflg[0] = (mn > q0 + QT - 1);
        }
        __syncthreads();
        if (sflg[0]) continue;   // uniform branch

        for (int idx = tid; idx < KT * 32; idx += 256) {
            int kj = idx >> 5;
            int c4 = (idx & 31) << 2;
            const float* kp = &g_qkv[(size_t)toks[kj] * NQKV + HQ * HD + hl * HD];
            float4 kv = *(const float4*)(kp + c4);
            Kt[(c4 + 0) * 33 + kj] = kv.x;
            Kt[(c4 + 1) * 33 + kj] = kv.y;
            Kt[(c4 + 2) * 33 + kj] = kv.z;
            Kt[(c4 + 3) * 33 + kj] = kv.w;
            float4 vv = *(const float4*)(kp + HKV * HD + c4);
            *(float4*)&Vs[kj * 128 + c4] = vv;
        }
        __syncthreads();

        float sr[4][2];
#pragma unroll
        for (int i = 0; i < 4; ++i) { sr[i][0] = 0.f; sr[i][1] = 0.f; }
#pragma unroll 4
        for (int d = 0; d < HD; ++d) {
            float b0 = Kt[d * 33 + (tx << 1)];
            float b1 = Kt[d * 33 + (tx << 1) + 1];
#pragma unroll
            for (int i = 0; i < 4; ++i) {
                float a = Qs[(ty * 4 + i) * 129 + d];
                sr[i][0] += a * b0;
                sr[i][1] += a * b1;
            }
        }
#pragma unroll
        for (int i = 0; i < 4; ++i) {
            int sq = q0 + ty * 4 + i;
#pragma unroll
            for (int j = 0; j < 2; ++j) {
                int tk = toks[(tx << 1) + j];
                Pp[(ty * 4 + i) * 33 + (tx << 1) + j] = (tk <= sq) ? sr[i][j] : NEGF;
            }
        }
        __syncthreads();

        if (tid < QT) {
            float mo = mrow[tid];
            float mt = mo;
#pragma unroll 8
            for (int j = 0; j < KT; ++j) mt = fmaxf(mt, Pp[tid * 33 + j]);
            float cc = __expf(mo - mt);
            float ls = 0.f;
#pragma unroll 4
            for (int j = 0; j < KT; ++j) {
                float pv = Pp[tid * 33 + j];
                float e  = (pv > -1e29f) ? __expf(pv - mt) : 0.f;
                Pp[tid * 33 + j] = e;
                ls += e;
            }
            lrow[tid] = lrow[tid] * cc + ls;
            mrow[tid] = mt;
            crow[tid] = cc;
        }
        __syncthreads();

        float cc4[4];
#pragma unroll
        for (int i = 0; i < 4; ++i) cc4[i] = crow[ty * 4 + i];
#pragma unroll
        for (int i = 0; i < 4; ++i)
#pragma unroll
            for (int j = 0; j < 8; ++j) acc[i][j] *= cc4[i];

        for (int kj = 0; kj < KT; ++kj) {
            float4 v0 = *(const float4*)&Vs[kj * 128 + (tx << 3)];
            float4 v1 = *(const float4*)&Vs[kj * 128 + (tx << 3) + 4];
#pragma unroll
            for (int i = 0; i < 4; ++i) {
                float p = Pp[(ty * 4 + i) * 33 + kj];
                acc[i][0] += p * v0.x; acc[i][1] += p * v0.y;
                acc[i][2] += p * v0.z; acc[i][3] += p * v0.w;
                acc[i][4] += p * v1.x; acc[i][5] += p * v1.y;
                acc[i][6] += p * v1.z; acc[i][7] += p * v1.w;
            }
        }
    }

    // writeout: direct bf16 hi/lo (same rounding as in-GEMM conversion before)
#pragma unroll
    for (int i = 0; i < 4; ++i) {
        float inv = 1.f / lrow[ty * 4 + i];
        float ov[8];
#pragma unroll
        for (int j = 0; j < 8; ++j) ov[j] = acc[i][j] * inv;
        uint32_t hw[4], lw[4];
#pragma unroll
        for (int q = 0; q < 4; ++q) {
            __nv_bfloat16 h0 = __float2bfloat16(ov[2 * q]);
            __nv_bfloat16 h1 = __float2bfloat16(ov[2 * q + 1]);
            __nv_bfloat16 l0 = __float2bfloat16(ov[2 * q]     - __bfloat162float(h0));
            __nv_bfloat16 l1 = __float2bfloat16(ov[2 * q + 1] - __bfloat162float(h1));
            hw[q] = ((uint32_t)__bfloat16_as_ushort(h1) << 16) | __bfloat16_as_ushort(h0);
            lw[q] = ((uint32_t)__bfloat16_as_ushort(l1) << 16) | __bfloat16_as_ushort(l0);
        }
        size_t base = (size_t)(q0 + ty * 4 + i) * DIMM + h * HD + (tx << 3);
        *(uint4*)&g_ath[base] = make_uint4(hw[0], hw[1], hw[2], hw[3]);
        *(uint4*)&g_atl[base] = make_uint4(lw[0], lw[1], lw[2], lw[3]);
    }
}

// ---------------------------------------------------------------------------
// Host launcher
// ---------------------------------------------------------------------------
extern "C" void kernel_launch(void* const* d_in, const int* in_sizes, int n_in,
                              void* d_out, int out_size)
{
    (void)in_sizes; (void)n_in; (void)out_size;
    const float* x    = (const float*)d_in[0];   // (1, S, DIM)
    const float* fc   = (const float*)d_in[1];   // (S, 64, 2)
    const float* wqkv = (const float*)d_in[2];   // (6144, 4096)
    const float* wo   = (const float*)d_in[3];   // (4096, 4096)
    float* y = (float*)d_out;                    // (1, S, DIM)

    float* qkv_p = nullptr;
    __nv_bfloat16 *xh, *xl, *wqh, *wql, *woh, *wol, *ath, *atl;
    cudaGetSymbolAddress((void**)&qkv_p, g_qkv);
    cudaGetSymbolAddress((void**)&xh,  g_xh);  cudaGetSymbolAddress((void**)&xl,  g_xl);
    cudaGetSymbolAddress((void**)&wqh, g_wqh); cudaGetSymbolAddress((void**)&wql, g_wql);
    cudaGetSymbolAddress((void**)&woh, g_woh); cudaGetSymbolAddress((void**)&wol, g_wol);
    cudaGetSymbolAddress((void**)&ath, g_ath); cudaGetSymbolAddress((void**)&atl, g_atl);

    cudaFuncSetAttribute(attn_kernel, cudaFuncAttributeMaxDynamicSharedMemorySize, SMEM_ATTN);
    cudaFuncSetAttribute(gemm_bf16,   cudaFuncAttributeMaxDynamicSharedMemorySize, SMEM_GEMM);

    // 0. split inputs to bf16 hi/lo (one-time, memory-bound, ~100us total)
    {
        int n4x = (S * DIMM) / 4;
        split_kernel<<<(n4x + 255) / 256, 256>>>(x, xh, xl, n4x);
        int n4q = (NQKV * DIMM) / 4;
        split_kernel<<<(n4q + 255) / 256, 256>>>(wqkv, wqh, wql, n4q);
        int n4o = (DIMM * DIMM) / 4;
        split_kernel<<<(n4o + 255) / 256, 256>>>(wo, woh, wol, n4o);
    }

    // 1. QKV projection: (4096 x 4096) @ (6144 x 4096)^T  -> bf16x3 mma.sync
    gemm_bf16<<<dim3(NQKV / 128, S / 128), 256, SMEM_GEMM>>>(xh, xl, wqh, wql, qkv_p, NQKV, DIMM);

    // 2. RoPE on q and k (in place)
    {
        int total = S * 40 * 64;
        rope_kernel<<<(total + 255) / 256, 256>>>(fc);
    }

    // 3. per-block key means + query mean (2-stage deterministic)
    kmean_kernel<<<(TB * HKV * HD) / 256, 256>>>();
    qmean_part_kernel<<<dim3(HQ, 16), 128>>>();
    qmean_final_kernel<<<(HQ * HD) / 128, 128>>>();

    // 4. scores + top-k block selection
    scores_topk_kernel<<<HQ, TB>>>();

    // 5. sparse causal attention (writes bf16 hi/lo directly)
    attn_kernel<<<dim3(S / QT, HQ), 256, SMEM_ATTN>>>();

    // 6. output projection: (4096 x 4096) @ (4096 x 4096)^T -> bf16x3 mma.sync
    gemm_bf16<<<dim3(DIMM / 128, S / 128), 256, SMEM_GEMM>>>(ath, atl, woh, wol, y, DIMM, DIMM);
}

// round 5
// speedup vs baseline: 2.4949x; 1.3348x over previous
#include <cuda_runtime.h>
#include <cuda_bf16.h>
#include <cstdint>

// ---------------------------------------------------------------------------
// Problem constants (fixed shapes)
// ---------------------------------------------------------------------------
#define S      4096
#define DIMM   4096
#define HQ     32
#define HKV    8
#define HD     128
#define NQKV   6144          // (HQ + 2*HKV) * HD
#define TB     512           // S / 8 blocks
#define SINKB  4             // ceil(30/8)
#define WINST  508           // window start block
#define MBTOP  100           // heavy blocks
#define KLBLK  108           // 4 sink + 4 window + 100 heavy
#define KSEL   (KLBLK * 8)   // 864 selected tokens per head
#define NEGF   (-1e30f)
#define SCALE  0.08838834764831845f   // 1/sqrt(128)

// ---------------------------------------------------------------------------
// Scratch (static device globals — no runtime allocation allowed)
// ---------------------------------------------------------------------------
__device__ float g_qkv[(size_t)S * NQKV];     // qkv projections (q/k roped in-place)
__device__ float g_krep[TB * HKV * HD];       // per-block mean keys
__device__ float g_qmean[HQ * HD];            // mean query per head
__device__ float g_qpart[16][HQ * HD];        // partial q sums (deterministic 2-stage)
__device__ int   g_blk[HQ * KLBLK];           // selected block ids per head

// bf16 hi/lo split operands
__device__ __align__(16) __nv_bfloat16 g_xh[(size_t)S * DIMM];
__device__ __align__(16) __nv_bfloat16 g_xl[(size_t)S * DIMM];
__device__ __align__(16) __nv_bfloat16 g_wqh[(size_t)NQKV * DIMM];
__device__ __align__(16) __nv_bfloat16 g_wql[(size_t)NQKV * DIMM];
__device__ __align__(16) __nv_bfloat16 g_woh[(size_t)DIMM * DIMM];
__device__ __align__(16) __nv_bfloat16 g_wol[(size_t)DIMM * DIMM];
__device__ __align__(16) __nv_bfloat16 g_ath[(size_t)S * DIMM];   // attention out hi
__device__ __align__(16) __nv_bfloat16 g_atl[(size_t)S * DIMM];   // attention out lo
__device__ __align__(16) __nv_bfloat16 g_qh[(size_t)S * NQKV];    // roped qkv hi
__device__ __align__(16) __nv_bfloat16 g_ql[(size_t)S * NQKV];    // roped qkv lo

// ---------------------------------------------------------------------------
// asm helpers (base-ISA only; no tcgen05 on this toolchain)
// ---------------------------------------------------------------------------
__device__ __forceinline__ uint32_t smem_to_u32(const void* smem_ptr) {
    uint32_t addr;
    asm("{ .reg .u64 tmp; cvta.to.shared.u64 tmp, %1; cvt.u32.u64 %0, tmp; }"
        : "=r"(addr) : "l"(smem_ptr));
    return addr;
}

__device__ __forceinline__ void ldsm4(uint32_t* r, uint32_t addr) {
    asm volatile("ldmatrix.sync.aligned.m8n8.x4.shared.b16 {%0,%1,%2,%3}, [%4];"
        : "=r"(r[0]), "=r"(r[1]), "=r"(r[2]), "=r"(r[3]) : "r"(addr));
}

__device__ __forceinline__ void ldsm4t(uint32_t* r, uint32_t addr) {
    asm volatile("ldmatrix.sync.aligned.m8n8.x4.trans.shared.b16 {%0,%1,%2,%3}, [%4];"
        : "=r"(r[0]), "=r"(r[1]), "=r"(r[2]), "=r"(r[3]) : "r"(addr));
}

__device__ __forceinline__ void mma_bf16(float* d, const uint32_t* a, const uint32_t* b) {
    asm volatile("mma.sync.aligned.m16n8k16.row.col.f32.bf16.bf16.f32 "
        "{%0,%1,%2,%3}, {%4,%5,%6,%7}, {%8,%9}, {%0,%1,%2,%3};"
        : "+f"(d[0]), "+f"(d[1]), "+f"(d[2]), "+f"(d[3])
        : "r"(a[0]), "r"(a[1]), "r"(a[2]), "r"(a[3]), "r"(b[0]), "r"(b[1]));
}

#define CP16(dst, src) \
    asm volatile("cp.async.cg.shared.global [%0], [%1], 16;" :: "r"(dst), "l"(src))
#define CP_COMMIT() asm volatile("cp.async.commit_group;" ::: "memory")
#define CP_WAIT(n)  asm volatile("cp.async.wait_group %0;" :: "n"(n) : "memory")

__device__ __forceinline__ uint32_t pack_bf16(float a, float b) {
    __nv_bfloat162 h = __floats2bfloat162_rn(a, b);
    return *(uint32_t*)&h;
}

// ---------------------------------------------------------------------------
// fp32 -> bf16 hi/lo split (pre-pass), float4 per thread
// ---------------------------------------------------------------------------
__global__ void split_kernel(const float* __restrict__ in,
                             __nv_bfloat16* __restrict__ hi,
                             __nv_bfloat16* __restrict__ lo, int n4)
{
    int i = blockIdx.x * blockDim.x + threadIdx.x;
    if (i >= n4) return;
    float4 v = ((const float4*)in)[i];
    __nv_bfloat16 h0 = __float2bfloat16(v.x);
    __nv_bfloat16 h1 = __float2bfloat16(v.y);
    __nv_bfloat16 h2 = __float2bfloat16(v.z);
    __nv_bfloat16 h3 = __float2bfloat16(v.w);
    __nv_bfloat16 l0 = __float2bfloat16(v.x - __bfloat162float(h0));
    __nv_bfloat16 l1 = __float2bfloat16(v.y - __bfloat162float(h1));
    __nv_bfloat16 l2 = __float2bfloat16(v.z - __bfloat162float(h2));
    __nv_bfloat16 l3 = __float2bfloat16(v.w - __bfloat162float(h3));
    uint2 H, L;
    H.x = ((uint32_t)__bfloat16_as_ushort(h1) << 16) | __bfloat16_as_ushort(h0);
    H.y = ((uint32_t)__bfloat16_as_ushort(h3) << 16) | __bfloat16_as_ushort(h2);
    L.x = ((uint32_t)__bfloat16_as_ushort(l1) << 16) | __bfloat16_as_ushort(l0);
    L.y = ((uint32_t)__bfloat16_as_ushort(l3) << 16) | __bfloat16_as_ushort(l2);
    ((uint2*)hi)[i] = H;
    ((uint2*)lo)[i] = L;
}

// ---------------------------------------------------------------------------
// Tensor-core GEMM (unchanged from round 4)
// ---------------------------------------------------------------------------
#define LDS_ROW 40                      // bf16 elems per smem row (80 bytes)
#define TILE_BYTES (128 * LDS_ROW * 2)  // 10240 per matrix variant
#define AHI_OFF 0
#define ALO_OFF (TILE_BYTES)
#define BHI_OFF (2 * TILE_BYTES)
#define BLO_OFF (3 * TILE_BYTES)
#define GBUF_BYTES (4 * TILE_BYTES)     // 40960
#define SMEM_GEMM (2 * GBUF_BYTES)      // 81920

#define GEMM_ISSUE(cc, boff) do {                                              \
    const int kb_ = (cc) << 5;                                                 \
    _Pragma("unroll")                                                          \
    for (int i_ = 0; i_ < 2; ++i_) {                                           \
        int u_   = tid + (i_ << 8);                                            \
        int row_ = u_ >> 2;                                                    \
        int seg_ = (u_ & 3) << 3;                                              \
        uint32_t d_ = sbase + (boff) +                                         \
                      (uint32_t)(row_ * (LDS_ROW * 2) + (seg_ << 1));          \
        CP16(d_ + AHI_OFF, Ah + (size_t)(bm + row_) * K + kb_ + seg_);         \
        CP16(d_ + ALO_OFF, Al + (size_t)(bm + row_) * K + kb_ + seg_);         \
        CP16(d_ + BHI_OFF, Bh + (size_t)(bn + row_) * K + kb_ + seg_);         \
        CP16(d_ + BLO_OFF, Bl + (size_t)(bn + row_) * K + kb_ + seg_);         \
    }                                                                          \
} while (0)

__global__ __launch_bounds__(256, 1)
void gemm_bf16(const __nv_bfloat16* __restrict__ Ah, const __nv_bfloat16* __restrict__ Al,
               const __nv_bfloat16* __restrict__ Bh, const __nv_bfloat16* __restrict__ Bl,
               float* __restrict__ C, int N, int K)
{
    extern __shared__ char smc[];
    const uint32_t sbase = smem_to_u32(smc);
    const int tid  = threadIdx.x;
    const int lane = tid & 31;
    const int wid  = tid >> 5;
    const int wm0  = (wid >> 2) << 6;
    const int wn0  = (wid & 3) << 5;
    const int bm   = blockIdx.y << 7;
    const int bn   = blockIdx.x << 7;

    float acc[4][4][4];
#pragma unroll
    for (int i = 0; i < 4; ++i)
#pragma unroll
        for (int j = 0; j < 4; ++j)
#pragma unroll
            for (int q = 0; q < 4; ++q) acc[i][j][q] = 0.f;

    const int nch = K >> 5;
    const int a_row  = lane & 15;
    const int a_col8 = (lane >> 4) << 3;
    const int b_row  = (lane & 7) + (((lane >> 4) & 1) << 3);
    const int b_col8 = ((lane >> 3) & 1) << 3;

    GEMM_ISSUE(0, 0u);
    CP_COMMIT();

    for (int c = 0; c < nch; ++c) {
        const uint32_t boff = (c & 1) ? GBUF_BYTES : 0;

        if (c + 1 < nch) {
            const uint32_t nb = ((c + 1) & 1) ? GBUF_BYTES : 0u;
            GEMM_ISSUE(c + 1, nb);
            CP_COMMIT();
            CP_WAIT(1);
        } else {
            CP_WAIT(0);
        }
        __syncthreads();

#pragma unroll
        for (int ks = 0; ks < 2; ++ks) {
            uint32_t ahi[4][4], alo[4][4], bhi[2][4], blo[2][4];
            const int kc = (ks << 4);
#pragma unroll
            for (int mt = 0; mt < 4; ++mt) {
                uint32_t off = (uint32_t)(wm0 + (mt << 4) + a_row) * (LDS_ROW * 2)
                             + (uint32_t)(kc + a_col8) * 2;
                ldsm4(ahi[mt], sbase + boff + AHI_OFF + off);
                ldsm4(alo[mt], sbase + boff + ALO_OFF + off);
            }
#pragma unroll
            for (int np = 0; np < 2; ++np) {
                uint32_t off = (uint32_t)(wn0 + (np << 4) + b_row) * (LDS_ROW * 2)
                             + (uint32_t)(kc + b_col8) * 2;
                ldsm4(bhi[np], sbase + boff + BHI_OFF + off);
                ldsm4(blo[np], sbase + boff + BLO_OFF + off);
            }
#pragma unroll
            for (int mt = 0; mt < 4; ++mt) {
#pragma unroll
                for (int nt = 0; nt < 4; ++nt) {
                    const uint32_t* bh = &bhi[nt >> 1][(nt & 1) << 1];
                    const uint32_t* bl = &blo[nt >> 1][(nt & 1) << 1];
                    mma_bf16(acc[mt][nt], ahi[mt], bh);
                    mma_bf16(acc[mt][nt], ahi[mt], bl);
                    mma_bf16(acc[mt][nt], alo[mt], bh);
                }
            }
        }
        __syncthreads();
    }

    const int er = lane >> 2;
    const int ec = (lane & 3) << 1;
#pragma unroll
    for (int mt = 0; mt < 4; ++mt) {
#pragma unroll
        for (int nt = 0; nt < 4; ++nt) {
            int r0 = bm + wm0 + (mt << 4) + er;
            int c0 = bn + wn0 + (nt << 3) + ec;
            *(float2*)(C + (size_t)r0 * N + c0)       = make_float2(acc[mt][nt][0], acc[mt][nt][1]);
            *(float2*)(C + (size_t)(r0 + 8) * N + c0) = make_float2(acc[mt][nt][2], acc[mt][nt][3]);
        }
    }
}

// ---------------------------------------------------------------------------
// RoPE in-place on q and k slices of g_qkv. one thread per (s, head40, pair)
// ---------------------------------------------------------------------------
__global__ void rope_kernel(const float* __restrict__ fc)
{
    const int total = S * 40 * 64;
    int tid = blockIdx.x * blockDim.x + threadIdx.x;
    if (tid >= total) return;
    int j  = tid & 63;
    int r  = tid >> 6;
    int hh = r % 40;
    int s  = r / 40;
    float* p = &g_qkv[(size_t)s * NQKV + hh * HD + (j << 1)];
    float f0 = fc[s * HD + (j << 1)];
    float f1 = fc[s * HD + (j << 1) + 1];
    float x0 = p[0], x1 = p[1];
    p[0] = x0 * f0 - x1 * f1;
    p[1] = x1 * f0 + x0 * f1;
}

// ---------------------------------------------------------------------------
// Per-block key means (8 tokens per block)
// ---------------------------------------------------------------------------
__global__ void kmean_kernel()
{
    int idx = blockIdx.x * blockDim.x + threadIdx.x;
    int d  = idx & 127;
    int hl = (idx >> 7) & 7;
    int t  = idx >> 10;
    const float* p = &g_qkv[(size_t)(t * 8) * NQKV + HQ * HD + hl * HD + d];
    float s = 0.f;
#pragma unroll
    for (int i = 0; i < 8; ++i) s += p[(size_t)i * NQKV];
    g_krep[idx] = s * 0.125f;
}

// ---------------------------------------------------------------------------
// Mean query per head — deterministic 2-stage
// ---------------------------------------------------------------------------
__global__ void qmean_part_kernel()
{
    int h = blockIdx.x, chunk = blockIdx.y, d = threadIdx.x;
    const float* p = &g_qkv[(size_t)(chunk * 256) * NQKV + h * HD + d];
    float s = 0.f;
#pragma unroll 4
    for (int i = 0; i < 256; ++i) s += p[(size_t)i * NQKV];
    g_qpart[chunk][h * HD + d] = s;
}

__global__ void qmean_final_kernel()
{
    int idx = blockIdx.x * blockDim.x + threadIdx.x;
    float s = 0.f;
#pragma unroll
    for (int i = 0; i < 16; ++i) s += g_qpart[i][idx];
    g_qmean[idx] = s * (1.f / 4096.f);
}

// ---------------------------------------------------------------------------
// Scores + top-k block selection. One block per head, 512 threads.
// ---------------------------------------------------------------------------
__global__ void scores_topk_kernel()
{
    __shared__ float qm[HD];
    __shared__ float sc[TB];
    __shared__ float rv[TB];
    __shared__ int   ri[TB];

    const int h  = blockIdx.x;
    const int t  = threadIdx.x;
    const int hl = h >> 2;

    if (t < HD) qm[t] = g_qmean[h * HD + t];
    __syncthreads();

    float s = 0.f;
    const float* kr = &g_krep[(t * HKV + hl) * HD];
#pragma unroll 8
    for (int d = 0; d < HD; ++d) s += qm[d] * kr[d];
    s *= SCALE;

    bool masked = (t < SINKB) || (t >= WINST);
    sc[t] = masked ? NEGF : s;

    if (t < 4) {
        g_blk[h * KLBLK + t]     = t;
        g_blk[h * KLBLK + 4 + t] = WINST + t;
    }
    __syncthreads();

    for (int pick = 0; pick < MBTOP; ++pick) {
        rv[t] = sc[t];
        ri[t] = t;
        __syncthreads();
        for (int off = 256; off > 0; off >>= 1) {
            if (t < off) {
                float v2 = rv[t + off];
                int   i2 = ri[t + off];
                if (v2 > rv[t] || (v2 == rv[t] && i2 < ri[t])) { rv[t] = v2; ri[t] = i2; }
            }
            __syncthreads();
        }
        if (t == 0) {
            g_blk[h * KLBLK + 8 + pick] = ri[0];
            sc[ri[0]] = -2e30f;
        }
        __syncthreads();
    }
}

// ---------------------------------------------------------------------------
// Tensor-core flash attention over 864 selected tokens per head.
// grid = (S/64, HQ), 128 threads (4 warps, each owns 16 q-rows).
// QK^T and P.V run on mma.sync bf16x3; softmax on fragments via quad shuffles.
// ---------------------------------------------------------------------------
#define ASTRIDE 272                 // smem row stride in bytes (136 bf16)
#define QH_OFF  0
#define QL_OFF  17408
#define KH_OFF  34816
#define KL_OFF  43520
#define VH_OFF  52224
#define VL_OFF  60928
#define TOK_OFF 69632
#define FLG_OFF 69760
#define SMEM_ATTN 69824

__global__ __launch_bounds__(128)
void attn_mma_kernel()
{
    extern __shared__ char smb[];
    const uint32_t sb = smem_to_u32(smb);
    int* toks = (int*)(smb + TOK_OFF);
    int* sflg = (int*)(smb + FLG_OFF);

    const int tid  = threadIdx.x;
    const int lane = tid & 31;
    const int wid  = tid >> 5;
    const int h    = blockIdx.y;
    const int q0   = blockIdx.x << 6;
    const int hl   = h >> 2;
    const int m0   = wid << 4;          // warp's q-row base within tile

    const int er = lane >> 2;
    const int ec = (lane & 3) << 1;

    // load Q tile rows q0..q0+63, head slice (hi+lo)
    {
        const size_t qcol = (size_t)h * HD;
        for (int t = tid; t < 1024; t += 128) {
            int r = t >> 4, ch = t & 15;
            uint32_t d = sb + (uint32_t)(r * ASTRIDE + ch * 16);
            const size_t src = (size_t)(q0 + r) * NQKV + qcol + ch * 8;
            CP16(d + QH_OFF, g_qh + src);
            CP16(d + QL_OFF, g_ql + src);
        }
    }
    CP_COMMIT();

    float oacc[16][4];
#pragma unroll
    for (int i = 0; i < 16; ++i)
#pragma unroll
        for (int j = 0; j < 4; ++j) oacc[i][j] = 0.f;
    float mrow0 = NEGF, mrow1 = NEGF, lrow0 = 0.f, lrow1 = 0.f;

    CP_WAIT(0);
    __syncthreads();

    for (int kt = 0; kt < KSEL / 32; ++kt) {
        if (tid < 32) {
            int j = kt * 32 + tid;
            int b = g_blk[h * KLBLK + (j >> 3)];
            toks[tid] = (b << 3) + (j & 7);
        }
        __syncthreads();
        if (tid == 0) {
            int mn = toks[0];
#pragma unroll
            for (int i = 1; i < 32; ++i) mn = min(mn, toks[i]);
            sflg[0] = (mn > q0 + 63);
        }
        __syncthreads();
        if (sflg[0]) continue;

        // gather K/V rows (hi+lo) via cp.async
        {
            const size_t kcol = (size_t)HQ * HD + (size_t)hl * HD;
            for (int t = tid; t < 512; t += 128) {
                int r = t >> 4, ch = t & 15;
                size_t src = (size_t)toks[r] * NQKV + kcol + ch * 8;
                uint32_t d = sb + (uint32_t)(r * ASTRIDE + ch * 16);
                CP16(d + KH_OFF, g_qh + src);
                CP16(d + KL_OFF, g_ql + src);
                CP16(d + VH_OFF, g_qh + src + HKV * HD);
                CP16(d + VL_OFF, g_ql + src + HKV * HD);
            }
        }
        CP_COMMIT(); CP_WAIT(0);
        __syncthreads();

        // ---- scores: S = Q @ K^T (64x32), bf16x3 ----
        float sc[4][4];
#pragma unroll
        for (int i = 0; i < 4; ++i)
#pragma unroll
            for (int j = 0; j < 4; ++j) sc[i][j] = 0.f;

#pragma unroll
        for (int ks = 0; ks < 8; ++ks) {
            const int kc = ks << 4;
            uint32_t ah[4], al[4], kh0[4], kl0[4], kh1[4], kl1[4];
            uint32_t aoff = (uint32_t)((m0 + (lane & 15)) * ASTRIDE)
                          + (uint32_t)((kc + ((lane >> 4) << 3)) * 2);
            ldsm4(ah, sb + QH_OFF + aoff);
            ldsm4(al, sb + QL_OFF + aoff);
            uint32_t boff = (uint32_t)((((lane & 7) + (((lane >> 4) & 1) << 3)) * ASTRIDE))
                          + (uint32_t)((kc + (((lane >> 3) & 1) << 3)) * 2);
            ldsm4(kh0, sb + KH_OFF + boff);
            ldsm4(kl0, sb + KL_OFF + boff);
            ldsm4(kh1, sb + KH_OFF + boff + 16 * ASTRIDE);
            ldsm4(kl1, sb + KL_OFF + boff + 16 * ASTRIDE);
#pragma unroll
            for (int nt = 0; nt < 4; ++nt) {
                const uint32_t* bh = (nt < 2) ? &kh0[(nt & 1) << 1] : &kh1[(nt & 1) << 1];
                const uint32_t* bl = (nt < 2) ? &kl0[(nt & 1) << 1] : &kl1[(nt & 1) << 1];
                mma_bf16(sc[nt], ah, bh);
                mma_bf16(sc[nt], ah, bl);
                mma_bf16(sc[nt], al, bh);
            }
        }

        // ---- scale + causal mask ----
        const int qr0 = q0 + m0 + er;
        const int qr1 = qr0 + 8;
#pragma unroll
        for (int nt = 0; nt < 4; ++nt) {
            int2 tt = *(int2*)&toks[(nt << 3) + ec];
            sc[nt][0] = (tt.x <= qr0) ? sc[nt][0] * SCALE : NEGF;
            sc[nt][1] = (tt.y <= qr0) ? sc[nt][1] * SCALE : NEGF;
            sc[nt][2] = (tt.x <= qr1) ? sc[nt][2] * SCALE : NEGF;
            sc[nt][3] = (tt.y <= qr1) ? sc[nt][3] * SCALE : NEGF;
        }

        // ---- online softmax on fragments (quad reductions) ----
        float mt0 = fmaxf(fmaxf(fmaxf(sc[0][0], sc[0][1]), fmaxf(sc[1][0], sc[1][1])),
                          fmaxf(fmaxf(sc[2][0], sc[2][1]), fmaxf(sc[3][0], sc[3][1])));
        float mt1 = fmaxf(fmaxf(fmaxf(sc[0][2], sc[0][3]), fmaxf(sc[1][2], sc[1][3])),
                          fmaxf(fmaxf(sc[2][2], sc[2][3]), fmaxf(sc[3][2], sc[3][3])));
        mt0 = fmaxf(mt0, __shfl_xor_sync(0xffffffffu, mt0, 1));
        mt0 = fmaxf(mt0, __shfl_xor_sync(0xffffffffu, mt0, 2));
        mt1 = fmaxf(mt1, __shfl_xor_sync(0xffffffffu, mt1, 1));
        mt1 = fmaxf(mt1, __shfl_xor_sync(0xffffffffu, mt1, 2));
        float mn0 = fmaxf(mrow0, mt0);
        float mn1 = fmaxf(mrow1, mt1);
        float cc0 = __expf(mrow0 - mn0);
        float cc1 = __expf(mrow1 - mn1);
        float ls0 = 0.f, ls1 = 0.f;
#pragma unroll
        for (int nt = 0; nt < 4; ++nt) {
            float p0 = (sc[nt][0] > -1e29f) ? __expf(sc[nt][0] - mn0) : 0.f;
            float p1 = (sc[nt][1] > -1e29f) ? __expf(sc[nt][1] - mn0) : 0.f;
            float p2 = (sc[nt][2] > -1e29f) ? __expf(sc[nt][2] - mn1) : 0.f;
            float p3 = (sc[nt][3] > -1e29f) ? __expf(sc[nt][3] - mn1) : 0.f;
            sc[nt][0] = p0; sc[nt][1] = p1; sc[nt][2] = p2; sc[nt][3] = p3;
            ls0 += p0 + p1; ls1 += p2 + p3;
        }
        ls0 += __shfl_xor_sync(0xffffffffu, ls0, 1);
        ls0 += __shfl_xor_sync(0xffffffffu, ls0, 2);
        ls1 += __shfl_xor_sync(0xffffffffu, ls1, 1);
        ls1 += __shfl_xor_sync(0xffffffffu, ls1, 2);
        lrow0 = lrow0 * cc0 + ls0;  mrow0 = mn0;
        lrow1 = lrow1 * cc1 + ls1;  mrow1 = mn1;

        // rescale existing accumulators
#pragma unroll
        for (int nt = 0; nt < 16; ++nt) {
            oacc[nt][0] *= cc0; oacc[nt][1] *= cc0;
            oacc[nt][2] *= cc1; oacc[nt][3] *= cc1;
        }

        // ---- pack P into A fragments (hi/lo) ----
        uint32_t ph[2][4], pl[2][4];
#pragma unroll
        for (int ks = 0; ks < 2; ++ks) {
#pragma unroll
            for (int hh = 0; hh < 2; ++hh) {
                int nt = (ks << 1) + hh;
                float p0 = sc[nt][0], p1 = sc[nt][1], p2 = sc[nt][2], p3 = sc[nt][3];
                uint32_t h01 = pack_bf16(p0, p1);
                uint32_t h23 = pack_bf16(p2, p3);
                ph[ks][(hh << 1) + 0] = h01;
                ph[ks][(hh << 1) + 1] = h23;
                __nv_bfloat162 b01 = *(__nv_bfloat162*)&h01;
                __nv_bfloat162 b23 = *(__nv_bfloat162*)&h23;
                pl[ks][(hh << 1) + 0] = pack_bf16(p0 - __bfloat162float(b01.x),
                                                  p1 - __bfloat162float(b01.y));
                pl[ks][(hh << 1) + 1] = pack_bf16(p2 - __bfloat162float(b23.x),
                                                  p3 - __bfloat162float(b23.y));
            }
        }

        // ---- O += P @ V (64x128), bf16x3 ----
#pragma unroll
        for (int ks = 0; ks < 2; ++ks) {
#pragma unroll
            for (int ng = 0; ng < 8; ++ng) {
                uint32_t vh[4], vl[4];
                uint32_t voff = (uint32_t)(((ks << 4) + (lane & 15)) * ASTRIDE)
                              + (uint32_t)(((ng << 4) + ((lane >> 4) << 3)) * 2);
                ldsm4t(vh, sb + VH_OFF + voff);
                ldsm4t(vl, sb + VL_OFF + voff);
                mma_bf16(oacc[2 * ng],     ph[ks], &vh[0]);
                mma_bf16(oacc[2 * ng],     ph[ks], &vl[0]);
                mma_bf16(oacc[2 * ng],     pl[ks], &vh[0]);
                mma_bf16(oacc[2 * ng + 1], ph[ks], &vh[2]);
                mma_bf16(oacc[2 * ng + 1], ph[ks], &vl[2]);
                mma_bf16(oacc[2 * ng + 1], pl[ks], &vh[2]);
            }
        }
        __syncthreads();   // protect K/V smem before next tile's cp.async
    }

    // ---- epilogue: normalize, split to bf16 hi/lo, store ----
    const float inv0 = 1.f / lrow0;
    const float inv1 = 1.f / lrow1;
    const int row0 = q0 + m0 + er;
    const int row1 = row0 + 8;
#pragma unroll
    for (int nt = 0; nt < 16; ++nt) {
        int col = h * HD + (nt << 3) + ec;
        float o0 = oacc[nt][0] * inv0, o1 = oacc[nt][1] * inv0;
        float o2 = oacc[nt][2] * inv1, o3 = oacc[nt][3] * inv1;
        uint32_t h01 = pack_bf16(o0, o1);
        uint32_t h23 = pack_bf16(o2, o3);
        __nv_bfloat162 b01 = *(__nv_bfloat162*)&h01;
        __nv_bfloat162 b23 = *(__nv_bfloat162*)&h23;
        uint32_t l01 = pack_bf16(o0 - __bfloat162float(b01.x), o1 - __bfloat162float(b01.y));
        uint32_t l23 = pack_bf16(o2 - __bfloat162float(b23.x), o3 - __bfloat162float(b23.y));
        *(uint32_t*)&g_ath[(size_t)row0 * DIMM + col] = h01;
        *(uint32_t*)&g_atl[(size_t)row0 * DIMM + col] = l01;
        *(uint32_t*)&g_ath[(size_t)row1 * DIMM + col] = h23;
        *(uint32_t*)&g_atl[(size_t)row1 * DIMM + col] = l23;
    }
}

// ---------------------------------------------------------------------------
// Host launcher
// ---------------------------------------------------------------------------
extern "C" void kernel_launch(void* const* d_in, const int* in_sizes, int n_in,
                              void* d_out, int out_size)
{
    (void)in_sizes; (void)n_in; (void)out_size;
    const float* x    = (const float*)d_in[0];
    const float* fc   = (const float*)d_in[1];
    const float* wqkv = (const float*)d_in[2];
    const float* wo   = (const float*)d_in[3];
    float* y = (float*)d_out;

    float* qkv_p = nullptr;
    __nv_bfloat16 *xh, *xl, *wqh, *wql, *woh, *wol, *ath, *atl, *qh, *ql;
    cudaGetSymbolAddress((void**)&qkv_p, g_qkv);
    cudaGetSymbolAddress((void**)&xh,  g_xh);  cudaGetSymbolAddress((void**)&xl,  g_xl);
    cudaGetSymbolAddress((void**)&wqh, g_wqh); cudaGetSymbolAddress((void**)&wql, g_wql);
    cudaGetSymbolAddress((void**)&woh, g_woh); cudaGetSymbolAddress((void**)&wol, g_wol);
    cudaGetSymbolAddress((void**)&ath, g_ath); cudaGetSymbolAddress((void**)&atl, g_atl);
    cudaGetSymbolAddress((void**)&qh,  g_qh);  cudaGetSymbolAddress((void**)&ql,  g_ql);

    cudaFuncSetAttribute(attn_mma_kernel, cudaFuncAttributeMaxDynamicSharedMemorySize, SMEM_ATTN);
    cudaFuncSetAttribute(gemm_bf16,       cudaFuncAttributeMaxDynamicSharedMemorySize, SMEM_GEMM);

    // 0. split GEMM inputs to bf16 hi/lo
    {
        int n4x = (S * DIMM) / 4;
        split_kernel<<<(n4x + 255) / 256, 256>>>(x, xh, xl, n4x);
        int n4q = (NQKV * DIMM) / 4;
        split_kernel<<<(n4q + 255) / 256, 256>>>(wqkv, wqh, wql, n4q);
        int n4o = (DIMM * DIMM) / 4;
        split_kernel<<<(n4o + 255) / 256, 256>>>(wo, woh, wol, n4o);
    }

    // 1. QKV projection
    gemm_bf16<<<dim3(NQKV / 128, S / 128), 256, SMEM_GEMM>>>(xh, xl, wqh, wql, qkv_p, NQKV, DIMM);

    // 2. RoPE in place
    {
        int total = S * 40 * 64;
        rope_kernel<<<(total + 255) / 256, 256>>>(fc);
    }

    // 2b. split roped qkv to bf16 hi/lo (feeds tensor-core attention)
    {
        int n4 = (S * NQKV) / 4;
        split_kernel<<<(n4 + 255) / 256, 256>>>(qkv_p, qh, ql, n4);
    }

    // 3. per-block key means + query mean
    kmean_kernel<<<(TB * HKV * HD) / 256, 256>>>();
    qmean_part_kernel<<<dim3(HQ, 16), 128>>>();
    qmean_final_kernel<<<(HQ * HD) / 128, 128>>>();

    // 4. scores + top-k block selection
    scores_topk_kernel<<<HQ, TB>>>();

    // 5. tensor-core sparse causal attention (writes bf16 hi/lo)
    attn_mma_kernel<<<dim3(S / 64, HQ), 128, SMEM_ATTN>>>();

    // 6. output projection
    gemm_bf16<<<dim3(DIMM / 128, S / 128), 256, SMEM_GEMM>>>(ath, atl, woh, wol, y, DIMM, DIMM);
}